// round 11
// baseline (speedup 1.0000x reference)
#include <cuda_runtime.h>
#include <cuda_fp16.h>
#include <math.h>

#define BB 16
#define CC 64
#define HWN 4096

// output layout (floats): l1,l2,p1,p2,gfeat,context
#define OUT_L1 0
#define OUT_L2 96
#define OUT_P1 192
#define OUT_P2 288
#define OUT_GF 384
#define OUT_CTX 4480

// scratch (device globals: no allocations allowed)
__device__ unsigned g_q[BB*HWN*4];     // half2 [b][n][d/2], pre-scaled by log2e/sqrt(8)
__device__ unsigned g_k[BB*HWN*4];     // half2 [b][n][d/2]
__device__ __half   g_v[BB*CC*HWN];    // half  [b][c][n]
__device__ float g_p1[BB*CC*64];       // pooled 8x8
__device__ float g_c1[BB*128*64];      // conv1 out 8x8
__device__ float g_c2[BB*256*16];      // conv2 out 4x4

__device__ __forceinline__ void mma_f16_k8(
    float& d0, float& d1, float& d2, float& d3,
    unsigned a0, unsigned a1, unsigned b0)
{
    asm volatile(
        "mma.sync.aligned.m16n8k8.row.col.f32.f16.f16.f32 "
        "{%0,%1,%2,%3}, {%4,%5}, {%6}, {%0,%1,%2,%3};\n"
        : "+f"(d0), "+f"(d1), "+f"(d2), "+f"(d3)
        : "r"(a0), "r"(a1), "r"(b0));
}

__device__ __forceinline__ void mma_f16_k16(
    float* d,
    unsigned a0, unsigned a1, unsigned a2, unsigned a3,
    unsigned b0, unsigned b1)
{
    asm volatile(
        "mma.sync.aligned.m16n8k16.row.col.f32.f16.f16.f32 "
        "{%0,%1,%2,%3}, {%4,%5,%6,%7}, {%8,%9}, {%0,%1,%2,%3};\n"
        : "+f"(d[0]), "+f"(d[1]), "+f"(d[2]), "+f"(d[3])
        : "r"(a0), "r"(a1), "r"(a2), "r"(a3), "r"(b0), "r"(b1));
}

__device__ __forceinline__ unsigned pack2(float lo, float hi) {
    __half2 h = __floats2half2_rn(lo, hi);
    return reinterpret_cast<unsigned&>(h);
}
__device__ __forceinline__ unsigned cvt_h2(float lo, float hi) {
    unsigned r;
    asm("cvt.rn.f16x2.f32 %0, %1, %2;" : "=r"(r) : "f"(hi), "f"(lo));
    return r;
}
__device__ __forceinline__ unsigned ex2_h2(unsigned x) {
    unsigned r;
    asm("ex2.approx.f16x2 %0, %1;" : "=r"(r) : "r"(x));
    return r;
}
__device__ __forceinline__ unsigned hadd2u(unsigned a, unsigned b) {
    unsigned r;
    asm("add.f16x2 %0, %1, %2;" : "=r"(r) : "r"(a), "r"(b));
    return r;
}
__device__ __forceinline__ void ldsm_x4(
    unsigned& r0, unsigned& r1, unsigned& r2, unsigned& r3, unsigned addr)
{
    asm volatile("ldmatrix.sync.aligned.m8n8.x4.shared.b16 {%0,%1,%2,%3}, [%4];"
                 : "=r"(r0), "=r"(r1), "=r"(r2), "=r"(r3) : "r"(addr));
}
__device__ __forceinline__ unsigned su32(const void* p) {
    return (unsigned)__cvta_generic_to_shared(p);
}
#define CP_ASYNC16(dst, src) \
    asm volatile("cp.async.cg.shared.global [%0], [%1], 16;" :: "r"(dst), "l"(src))
#define CP_COMMIT() asm volatile("cp.async.commit_group;")
#define CP_WAIT0()  asm volatile("cp.async.wait_group 0;" ::: "memory")

// QK mma + exp for one n16 block; accumulates fp16 denominator partials.
__device__ __forceinline__ void qk_exp(
    const unsigned* kf, int kb, unsigned qa0, unsigned qa1,
    unsigned* a, unsigned& h2s0, unsigned& h2s1)
{
    float s0=0.f,s1=0.f,s2=0.f,s3=0.f,s4=0.f,s5=0.f,s6=0.f,s7=0.f;
    mma_f16_k8(s0,s1,s2,s3, qa0,qa1, kf[2*kb]);
    mma_f16_k8(s4,s5,s6,s7, qa0,qa1, kf[2*kb+1]);
    a[0] = ex2_h2(cvt_h2(s0, s1));
    a[1] = ex2_h2(cvt_h2(s2, s3));
    a[2] = ex2_h2(cvt_h2(s4, s5));
    a[3] = ex2_h2(cvt_h2(s6, s7));
    h2s0 = hadd2u(h2s0, hadd2u(a[0], a[2]));
    h2s1 = hadd2u(h2s1, hadd2u(a[1], a[3]));
}

// ---------------------------------------------------------------------------
// nop spacer kernels (profiler alignment: attn at launch position 4)
// ---------------------------------------------------------------------------
__global__ void nop_kernel() {}

// ---------------------------------------------------------------------------
// QKV: fused 1x1 convs. thread = (b, 2 adjacent pixels). Outputs fp16.
// ---------------------------------------------------------------------------
__global__ void __launch_bounds__(128) qkv_kernel(
    const float* __restrict__ f,
    const float* __restrict__ qw, const float* __restrict__ qb,
    const float* __restrict__ kw, const float* __restrict__ kb,
    const float* __restrict__ vw, const float* __restrict__ vb)
{
    __shared__ float qws[512], kws[512], vws[4096];
    __shared__ float qbs[8], kbs[8], vbs[64];
    const int tid = threadIdx.x;
    for (int i = tid; i < 512; i += 128) { qws[i] = qw[i]; kws[i] = kw[i]; }
    for (int i = tid; i < 4096; i += 128) vws[i] = vw[i];
    if (tid < 8)  { qbs[tid] = qb[tid]; kbs[tid] = kb[tid]; }
    if (tid < 64) vbs[tid] = vb[tid];
    __syncthreads();

    const int gid = blockIdx.x * 128 + tid;      // 32768 pairs
    const int b = gid >> 11;
    const int n = (gid & 2047) << 1;             // even pixel

    float2 qa[8], ka[8], va[64];
#pragma unroll
    for (int i = 0; i < 8; i++) {
        qa[i] = make_float2(qbs[i], qbs[i]);
        ka[i] = make_float2(kbs[i], kbs[i]);
    }
#pragma unroll
    for (int j = 0; j < 64; j++) va[j] = make_float2(vbs[j], vbs[j]);

    const float* fp = f + (size_t)b * CC * HWN + n;
#pragma unroll 4
    for (int c = 0; c < 64; c++) {
        const float2 fv = *(const float2*)(fp + (size_t)c * HWN);
#pragma unroll
        for (int i = 0; i < 8; i++) {
            const float wq = qws[i*64 + c], wk = kws[i*64 + c];
            qa[i].x += wq * fv.x; qa[i].y += wq * fv.y;
            ka[i].x += wk * fv.x; ka[i].y += wk * fv.y;
        }
#pragma unroll
        for (int j = 0; j < 64; j++) {
            const float wv = vws[j*64 + c];
            va[j].x += wv * fv.x; va[j].y += wv * fv.y;
        }
    }
    const float ss = 0.51006975f;   // log2(e)/sqrt(8)
    uint4 u;
    u.x = pack2(qa[0].x*ss, qa[1].x*ss); u.y = pack2(qa[2].x*ss, qa[3].x*ss);
    u.z = pack2(qa[4].x*ss, qa[5].x*ss); u.w = pack2(qa[6].x*ss, qa[7].x*ss);
    ((uint4*)g_q)[b*HWN + n] = u;
    u.x = pack2(qa[0].y*ss, qa[1].y*ss); u.y = pack2(qa[2].y*ss, qa[3].y*ss);
    u.z = pack2(qa[4].y*ss, qa[5].y*ss); u.w = pack2(qa[6].y*ss, qa[7].y*ss);
    ((uint4*)g_q)[b*HWN + n + 1] = u;
    u.x = pack2(ka[0].x, ka[1].x); u.y = pack2(ka[2].x, ka[3].x);
    u.z = pack2(ka[4].x, ka[5].x); u.w = pack2(ka[6].x, ka[7].x);
    ((uint4*)g_k)[b*HWN + n] = u;
    u.x = pack2(ka[0].y, ka[1].y); u.y = pack2(ka[2].y, ka[3].y);
    u.z = pack2(ka[4].y, ka[5].y); u.w = pack2(ka[6].y, ka[7].y);
    ((uint4*)g_k)[b*HWN + n + 1] = u;
#pragma unroll
    for (int c = 0; c < 64; c++) {
        const unsigned h2 = pack2(va[c].x, va[c].y);
        *(unsigned*)(g_v + ((size_t)(b*CC + c))*HWN + n) = h2;
    }
}

// ---------------------------------------------------------------------------
// Flash-fused attention + conv_o + residual (fp16 mma, P in regs, cp.async V).
// exp/PV software pipeline + next-tile K-fragment register prefetch.
// ---------------------------------------------------------------------------
#define VROWB   272
#define VBUFB   (64*VROWB)
#define PS_STRIDE 132
#define OW_S    68
#define SM_OWS  8448
#define SM_DEN  (SM_OWS + 64*OW_S)
#define ATTN_SMEM_FLOATS (SM_DEN + 128)
#define ATTN_SMEM_BYTES  (ATTN_SMEM_FLOATS * 4)

__global__ void __launch_bounds__(256, 2) attn_kernel(
    const float* __restrict__ feat,
    const float* __restrict__ ow, const float* __restrict__ ob,
    const float* __restrict__ scale, float* __restrict__ ctx)
{
    extern __shared__ float sm[];
    char* smc = (char*)sm;
    float* den = sm + SM_DEN;

    const int b   = blockIdx.x >> 5;
    const int q0  = (blockIdx.x & 31) * 128;
    const int tid = threadIdx.x;
    const int w   = tid >> 5;
    const int lane = tid & 31;
    const int g   = lane >> 2;
    const int t4  = lane & 3;

    const int qrow = q0 + w*16 + g;
    const unsigned qa0 = g_q[(b*HWN + qrow)*4 + t4];
    const unsigned qa1 = g_q[(b*HWN + qrow + 8)*4 + t4];

    float o[8][4];
#pragma unroll
    for (int i = 0; i < 8; i++)
#pragma unroll
        for (int j = 0; j < 4; j++) o[i][j] = 0.f;
    float dsum0 = 0.f, dsum1 = 0.f;

    const int vc  = tid >> 2;
    const int seg = tid & 3;
    const char* gv_src = (const char*)g_v
        + 2*(((size_t)(b*CC + vc))*HWN + seg*32);
    const unsigned vdst = su32(smc) + vc*VROWB + seg*64;

    const int lm_m = lane >> 3, lm_r = lane & 7;
    const unsigned lm_base = su32(smc)
        + ((lm_m >> 1)*8 + lm_r)*VROWB + (lm_m & 1)*16;

    {   // stage V tile 0
        const char* s = gv_src;
#pragma unroll
        for (int i = 0; i < 4; i++) CP_ASYNC16(vdst + i*16, s + i*16);
        CP_COMMIT();
    }

    const unsigned* gk = g_k + (b*HWN + g)*4 + t4;   // lane base
    // K fragments for tile 0 (prefetched into regs)
    unsigned kf[16];
#pragma unroll
    for (int i = 0; i < 16; i++) kf[i] = gk[(8*i) * 4];

    for (int kt = 0; kt < 32; kt++) {
        const int k0 = kt * 128;
        CP_WAIT0();
        __syncthreads();               // V(kt) visible; old buffer free

        if (kt < 31) {                 // stage V(kt+1)
            const char* s = gv_src + 2*(size_t)(k0 + 128);
            const unsigned d = vdst + ((kt + 1) & 1) * VBUFB;
#pragma unroll
            for (int i = 0; i < 4; i++) CP_ASYNC16(d + i*16, s + i*16);
            CP_COMMIT();
        }
        // prefetch K fragments for tile kt+1 (hidden under this tile's compute)
        unsigned kfn[16];
        if (kt < 31) {
#pragma unroll
            for (int i = 0; i < 16; i++) kfn[i] = gk[(k0 + 128 + 8*i) * 4];
        }

        const unsigned bufoff = (kt & 1) * VBUFB;
        unsigned h2s0 = 0, h2s1 = 0;

        // software pipeline: exp(kb+1) overlaps PV(kb)
        unsigned acur[4], anext[4];
        qk_exp(kf, 0, qa0, qa1, acur, h2s0, h2s1);
#pragma unroll
        for (int kb = 0; kb < 8; kb++) {
            if (kb < 7) qk_exp(kf, kb + 1, qa0, qa1, anext, h2s0, h2s1);
#pragma unroll
            for (int cbp = 0; cbp < 4; cbp++) {
                unsigned v0, v1, v2, v3;
                ldsm_x4(v0, v1, v2, v3,
                        lm_base + bufoff + cbp*(16*VROWB) + kb*32);
                mma_f16_k16(o[2*cbp],     acur[0],acur[1],acur[2],acur[3], v0, v1);
                mma_f16_k16(o[2*cbp + 1], acur[0],acur[1],acur[2],acur[3], v2, v3);
            }
#pragma unroll
            for (int j = 0; j < 4; j++) acur[j] = anext[j];
        }
        // roll K fragments (only when kfn is valid)
        if (kt < 31) {
#pragma unroll
            for (int i = 0; i < 16; i++) kf[i] = kfn[i];
        }

        const __half2 hh0 = *(__half2*)&h2s0;
        const __half2 hh1 = *(__half2*)&h2s1;
        const float2 f0 = __half22float2(hh0);
        const float2 f1 = __half22float2(hh1);
        dsum0 += f0.x + f0.y;
        dsum1 += f1.x + f1.y;
    }
    __syncthreads();

    dsum0 += __shfl_xor_sync(0xffffffffu, dsum0, 1);
    dsum0 += __shfl_xor_sync(0xffffffffu, dsum0, 2);
    dsum1 += __shfl_xor_sync(0xffffffffu, dsum1, 1);
    dsum1 += __shfl_xor_sync(0xffffffffu, dsum1, 2);
    if (t4 == 0) {
        den[w*16 + g]     = dsum0;
        den[w*16 + 8 + g] = dsum1;
    }

    float* attS = sm;
#pragma unroll
    for (int cb = 0; cb < 8; cb++) {
        const int cA = cb*8 + 2*t4;
        const int ql = w*16 + g;
        attS[cA*PS_STRIDE + ql]           = o[cb][0];
        attS[(cA+1)*PS_STRIDE + ql]       = o[cb][1];
        attS[cA*PS_STRIDE + ql + 8]       = o[cb][2];
        attS[(cA+1)*PS_STRIDE + ql + 8]   = o[cb][3];
    }
    float* owS = sm + SM_OWS;
#pragma unroll
    for (int i = 0; i < 16; i++) {
        const int idx = tid + i*256;
        owS[(idx & 63)*OW_S + (idx >> 6)] = ow[idx];
    }
    __syncthreads();

    const int oy = tid >> 5;
    const int qx = tid & 31;
    const float4 dv = *(const float4*)&den[qx*4];
    const float rd[4] = {1.f/dv.x, 1.f/dv.y, 1.f/dv.z, 1.f/dv.w};

    float oacc[8][4];
#pragma unroll
    for (int i = 0; i < 8; i++)
#pragma unroll
        for (int j = 0; j < 4; j++) oacc[i][j] = 0.f;

#pragma unroll 4
    for (int c = 0; c < 64; c++) {
        const float4 av = *(const float4*)&attS[c*PS_STRIDE + qx*4];
        const float4 w0 = *(const float4*)&owS[c*OW_S + oy*8];
        const float4 w1 = *(const float4*)&owS[c*OW_S + oy*8 + 4];
        const float wv[8] = {w0.x, w0.y, w0.z, w0.w, w1.x, w1.y, w1.z, w1.w};
#pragma unroll
        for (int i = 0; i < 8; i++) {
            oacc[i][0] += wv[i] * av.x;
            oacc[i][1] += wv[i] * av.y;
            oacc[i][2] += wv[i] * av.z;
            oacc[i][3] += wv[i] * av.w;
        }
    }
    const float sc = scale[0];
#pragma unroll
    for (int i = 0; i < 8; i++) {
        const int oc = oy*8 + i;
        const float obv = __ldg(&ob[oc]);
        const size_t base = ((size_t)(b*CC + oc)) * HWN + q0 + qx*4;
        const float4 f4 = *(const float4*)&feat[base];
        float4 r;
        r.x = f4.x + sc * (oacc[i][0]*rd[0] + obv);
        r.y = f4.y + sc * (oacc[i][1]*rd[1] + obv);
        r.z = f4.z + sc * (oacc[i][2]*rd[2] + obv);
        r.w = f4.w + sc * (oacc[i][3]*rd[3] + obv);
        *(float4*)&ctx[base] = r;
    }
}

// ---------------------------------------------------------------------------
// pool 64x64 -> 8x8 (one output per thread, 65536 threads)
// ---------------------------------------------------------------------------
__global__ void pool1_kernel(const float* __restrict__ ctx)
{
    const int gid = blockIdx.x * 256 + threadIdx.x;
    const int pix = gid & 63;
    const int ox = pix & 7, oy = pix >> 3;
    const int bc = gid >> 6;
    const float4* src = (const float4*)(ctx + (size_t)bc * HWN + oy*8*64 + ox*8);
    float s = 0.f;
#pragma unroll
    for (int r = 0; r < 8; r++) {
        const float4 a = src[r*16];
        const float4 c = src[r*16 + 1];
        s += (a.x + a.y + a.z + a.w) + (c.x + c.y + c.z + c.w);
    }
    g_p1[gid] = s * (1.f/64.f);
}

// ---------------------------------------------------------------------------
// conv1 3x3 SAME on 8x8, 64->128, bn, relu. padded 10x10 input.
// ---------------------------------------------------------------------------
__global__ void __launch_bounds__(128) conv1_kernel(
    const float* __restrict__ w, const float* __restrict__ bias,
    const float* __restrict__ bg, const float* __restrict__ bb,
    const float* __restrict__ bm, const float* __restrict__ bv)
{
    __shared__ float insp[64*100];
    __shared__ float ws[8*576];
    const int tid = threadIdx.x;
    const int b  = blockIdx.x >> 4;
    const int og = (blockIdx.x & 15) * 8;

    for (int i = tid; i < 6400; i += 128) insp[i] = 0.f;
    __syncthreads();
    for (int i = tid; i < 4096; i += 128) {
        const int ic = i >> 6, pix = i & 63;
        insp[ic*100 + ((pix >> 3) + 1)*10 + (pix & 7) + 1] = g_p1[b*4096 + i];
    }
    for (int i = tid; i < 4608; i += 128) ws[i] = w[og*576 + i];
    __syncthreads();

    const int ol   = tid >> 4;
    const int o    = og + ol;
    const int quad = tid & 15;
    const int y    = quad >> 1;
    const int xh   = (quad & 1) * 4;

    float acc[4] = {0.f, 0.f, 0.f, 0.f};
    const float* wp0 = ws + ol*576;
    const float* ip0 = insp + y*10 + xh;
    for (int ic = 0; ic < 64; ic++) {
        const float* wp = wp0 + ic*9;
        const float* ip = ip0 + ic*100;
        float w0 = wp[0], w1 = wp[1], w2 = wp[2];
        float w3 = wp[3], w4 = wp[4], w5 = wp[5];
        float w6 = wp[6], w7 = wp[7], w8 = wp[8];
        float r0[6], r1[6], r2[6];
#pragma unroll
        for (int j = 0; j < 6; j++) {
            r0[j] = ip[j]; r1[j] = ip[10 + j]; r2[j] = ip[20 + j];
        }
#pragma unroll
        for (int j = 0; j < 4; j++) {
            acc[j] += w0*r0[j] + w1*r0[j+1] + w2*r0[j+2]
                    + w3*r1[j] + w4*r1[j+1] + w5*r1[j+2]
                    + w6*r2[j] + w7*r2[j+1] + w8*r2[j+2];
        }
    }
    const float inv = bg[o] * rsqrtf(bv[o] + 1e-5f);
    const float sh  = bb[o] - bm[o]*inv;
    const float bo  = bias[o];
    float* dst = g_c1 + b*8192 + o*64 + y*8 + xh;
#pragma unroll
    for (int j = 0; j < 4; j++)
        dst[j] = fmaxf((acc[j] + bo)*inv + sh, 0.f);
}

// conv2 (with fused 8x8->4x4 pool) 3x3 SAME on 4x4, 128->256, bn, relu.
__global__ void __launch_bounds__(256) conv2_kernel(
    const float* __restrict__ w, const float* __restrict__ bias,
    const float* __restrict__ bg, const float* __restrict__ bb,
    const float* __restrict__ bm, const float* __restrict__ bv)
{
    __shared__ float ins[128*16];
    const int tid = threadIdx.x;
    const int b  = blockIdx.x >> 4;
    const int og = (blockIdx.x & 15) * 16;
    for (int i = tid; i < 2048; i += 256) {
        const int ic = i >> 4, pix = i & 15;
        const int py = pix >> 2, px = pix & 3;
        const float* src = g_c1 + (size_t)(b*128 + ic)*64 + (py*2)*8 + px*2;
        ins[i] = (src[0] + src[1] + src[8] + src[9]) * 0.25f;
    }
    __syncthreads();

    const int o   = og + (tid >> 4);
    const int pix = tid & 15;
    const int y = pix >> 2, x = pix & 3;
    float s = 0.f;
    for (int ic = 0; ic < 128; ic++) {
        const float* ip = ins + ic*16;
        const float* wp = w + ((size_t)o*128 + ic)*9;
#pragma unroll
        for (int ky = -1; ky <= 1; ky++) {
            const int yy = y + ky;
            if ((unsigned)yy < 4u) {
#pragma unroll
                for (int kx = -1; kx <= 1; kx++) {
                    const int xx = x + kx;
                    if ((unsigned)xx < 4u)
                        s += ip[yy*4 + xx] * __ldg(&wp[(ky+1)*3 + (kx+1)]);
                }
            }
        }
    }
    const float inv = bg[o] * rsqrtf(bv[o] + 1e-5f);
    const float r = (s + bias[o]) * inv + (bb[o] - bm[o]*inv);
    g_c2[b*4096 + o*16 + pix] = fmaxf(r, 0.f);
}

// gfeat + hierarchical heads.  block per batch.
__global__ void head_kernel(
    const float* __restrict__ w1, const float* __restrict__ b1,
    const float* __restrict__ w2, const float* __restrict__ b2,
    float* __restrict__ out)
{
    __shared__ float gfs[256];
    __shared__ float l1s[6], p1s[6], l2s[6];
    const int b = blockIdx.x, t = threadIdx.x;

    const float* p = g_c2 + b*4096 + t*16;
    float s = 0.f;
#pragma unroll
    for (int i = 0; i < 16; i++) s += p[i];
    s *= (1.f/16.f);
    gfs[t] = s;
    out[OUT_GF + b*256 + t] = s;
    __syncthreads();

    if (t < 6) {
        float a = b1[t];
        for (int c = 0; c < 256; c++) a += gfs[c] * w1[t*256 + c];
        l1s[t] = a;
        out[OUT_L1 + b*6 + t] = a;
    }
    __syncthreads();
    if (t == 0) {
        float mx = l1s[0];
#pragma unroll
        for (int i = 1; i < 6; i++) mx = fmaxf(mx, l1s[i]);
        float se = 0.f, e[6];
#pragma unroll
        for (int i = 0; i < 6; i++) { e[i] = __expf(l1s[i] - mx); se += e[i]; }
        const float rse = 1.f / se;
#pragma unroll
        for (int i = 0; i < 6; i++) {
            p1s[i] = e[i] * rse;
            out[OUT_P1 + b*6 + i] = p1s[i];
        }
    }
    __syncthreads();
    if (t < 6) {
        float a = b2[t];
        for (int c = 0; c < 256; c++) a += gfs[c] * w2[t*262 + c];
#pragma unroll
        for (int j = 0; j < 6; j++) a += p1s[j] * w2[t*262 + 256 + j];
        l2s[t] = a;
        out[OUT_L2 + b*6 + t] = a;
    }
    __syncthreads();
    if (t == 0) {
        float mx = l2s[0];
#pragma unroll
        for (int i = 1; i < 6; i++) mx = fmaxf(mx, l2s[i]);
        float se = 0.f, e[6];
#pragma unroll
        for (int i = 0; i < 6; i++) { e[i] = __expf(l2s[i] - mx); se += e[i]; }
        const float rse = 1.f / se;
#pragma unroll
        for (int i = 0; i < 6; i++) out[OUT_P2 + b*6 + i] = e[i] * rse;
    }
}

// ---------------------------------------------------------------------------
extern "C" void kernel_launch(void* const* d_in, const int* in_sizes, int n_in,
                              void* d_out, int out_size)
{
    (void)in_sizes; (void)n_in; (void)out_size;
    const float* feat = (const float*)d_in[0];
    const float* qw = (const float*)d_in[1];
    const float* qb = (const float*)d_in[2];
    const float* kw = (const float*)d_in[3];
    const float* kb = (const float*)d_in[4];
    const float* vw = (const float*)d_in[5];
    const float* vb = (const float*)d_in[6];
    const float* ow = (const float*)d_in[7];
    const float* ob = (const float*)d_in[8];
    const float* sc = (const float*)d_in[9];
    const float* c1w = (const float*)d_in[10];
    const float* c1b = (const float*)d_in[11];
    const float* bg1 = (const float*)d_in[12];
    const float* bb1 = (const float*)d_in[13];
    const float* bm1 = (const float*)d_in[14];
    const float* bv1 = (const float*)d_in[15];
    const float* c2w = (const float*)d_in[16];
    const float* c2b = (const float*)d_in[17];
    const float* bg2 = (const float*)d_in[18];
    const float* bb2 = (const float*)d_in[19];
    const float* bm2 = (const float*)d_in[20];
    const float* bv2 = (const float*)d_in[21];
    const float* w1 = (const float*)d_in[22];
    const float* b1 = (const float*)d_in[23];
    const float* w2 = (const float*)d_in[24];
    const float* b2 = (const float*)d_in[25];

    float* out = (float*)d_out;
    float* ctx = out + OUT_CTX;

    cudaFuncSetAttribute(attn_kernel,
                         cudaFuncAttributeMaxDynamicSharedMemorySize,
                         ATTN_SMEM_BYTES);

    qkv_kernel<<<256, 128>>>(feat, qw, qb, kw, kb, vw, vb);
    nop_kernel<<<1, 32>>>();
    nop_kernel<<<1, 32>>>();
    attn_kernel<<<512, 256, ATTN_SMEM_BYTES>>>(feat, ow, ob, sc, ctx);
    pool1_kernel<<<256, 256>>>(ctx);
    conv1_kernel<<<256, 128>>>(c1w, c1b, bg1, bb1, bm1, bv1);
    conv2_kernel<<<256, 256>>>(c2w, c2b, bg2, bb2, bm2, bv2);
    head_kernel<<<16, 256>>>(w1, b1, w2, b2, out);
}

// round 12
// speedup vs baseline: 1.0775x; 1.0775x over previous
#include <cuda_runtime.h>
#include <cuda_fp16.h>
#include <math.h>

#define BB 16
#define CC 64
#define HWN 4096

// output layout (floats): l1,l2,p1,p2,gfeat,context
#define OUT_L1 0
#define OUT_L2 96
#define OUT_P1 192
#define OUT_P2 288
#define OUT_GF 384
#define OUT_CTX 4480

// scratch (device globals: no allocations allowed)
__device__ unsigned g_q[BB*HWN*4];     // half2 [b][n][d/2], pre-scaled by log2e/sqrt(8)
__device__ unsigned g_k[BB*HWN*4];     // half2 [b][n][d/2]
__device__ __half   g_v[BB*CC*HWN];    // half  [b][c][n]
__device__ float g_p1[BB*CC*64];       // pooled 8x8
__device__ float g_c1[BB*128*64];      // conv1 out 8x8
__device__ float g_c2[BB*256*16];      // conv2 out 4x4

__device__ __forceinline__ void mma_f16_k8(
    float& d0, float& d1, float& d2, float& d3,
    unsigned a0, unsigned a1, unsigned b0)
{
    asm volatile(
        "mma.sync.aligned.m16n8k8.row.col.f32.f16.f16.f32 "
        "{%0,%1,%2,%3}, {%4,%5}, {%6}, {%0,%1,%2,%3};\n"
        : "+f"(d0), "+f"(d1), "+f"(d2), "+f"(d3)
        : "r"(a0), "r"(a1), "r"(b0));
}

__device__ __forceinline__ void mma_f16_k16(
    float* d,
    unsigned a0, unsigned a1, unsigned a2, unsigned a3,
    unsigned b0, unsigned b1)
{
    asm volatile(
        "mma.sync.aligned.m16n8k16.row.col.f32.f16.f16.f32 "
        "{%0,%1,%2,%3}, {%4,%5,%6,%7}, {%8,%9}, {%0,%1,%2,%3};\n"
        : "+f"(d[0]), "+f"(d[1]), "+f"(d[2]), "+f"(d[3])
        : "r"(a0), "r"(a1), "r"(a2), "r"(a3), "r"(b0), "r"(b1));
}

__device__ __forceinline__ unsigned pack2(float lo, float hi) {
    __half2 h = __floats2half2_rn(lo, hi);
    return reinterpret_cast<unsigned&>(h);
}
__device__ __forceinline__ unsigned cvt_h2(float lo, float hi) {
    unsigned r;
    asm("cvt.rn.f16x2.f32 %0, %1, %2;" : "=r"(r) : "f"(hi), "f"(lo));
    return r;
}
__device__ __forceinline__ unsigned ex2_h2(unsigned x) {
    unsigned r;
    asm("ex2.approx.f16x2 %0, %1;" : "=r"(r) : "r"(x));
    return r;
}
__device__ __forceinline__ unsigned hadd2u(unsigned a, unsigned b) {
    unsigned r;
    asm("add.f16x2 %0, %1, %2;" : "=r"(r) : "r"(a), "r"(b));
    return r;
}
__device__ __forceinline__ void ldsm_x4(
    unsigned& r0, unsigned& r1, unsigned& r2, unsigned& r3, unsigned addr)
{
    asm volatile("ldmatrix.sync.aligned.m8n8.x4.shared.b16 {%0,%1,%2,%3}, [%4];"
                 : "=r"(r0), "=r"(r1), "=r"(r2), "=r"(r3) : "r"(addr));
}
__device__ __forceinline__ unsigned su32(const void* p) {
    return (unsigned)__cvta_generic_to_shared(p);
}
#define CP_ASYNC16(dst, src) \
    asm volatile("cp.async.cg.shared.global [%0], [%1], 16;" :: "r"(dst), "l"(src))
#define CP_COMMIT() asm volatile("cp.async.commit_group;")
#define CP_WAIT0()  asm volatile("cp.async.wait_group 0;" ::: "memory")

// ---------------------------------------------------------------------------
// nop spacer kernels (profiler alignment: attn at launch position 4)
// ---------------------------------------------------------------------------
__global__ void nop_kernel() {}

// ---------------------------------------------------------------------------
// QKV: fused 1x1 convs. thread = (b, 2 adjacent pixels). Outputs fp16.
// ---------------------------------------------------------------------------
__global__ void __launch_bounds__(128) qkv_kernel(
    const float* __restrict__ f,
    const float* __restrict__ qw, const float* __restrict__ qb,
    const float* __restrict__ kw, const float* __restrict__ kb,
    const float* __restrict__ vw, const float* __restrict__ vb)
{
    __shared__ float qws[512], kws[512], vws[4096];
    __shared__ float qbs[8], kbs[8], vbs[64];
    const int tid = threadIdx.x;
    for (int i = tid; i < 512; i += 128) { qws[i] = qw[i]; kws[i] = kw[i]; }
    for (int i = tid; i < 4096; i += 128) vws[i] = vw[i];
    if (tid < 8)  { qbs[tid] = qb[tid]; kbs[tid] = kb[tid]; }
    if (tid < 64) vbs[tid] = vb[tid];
    __syncthreads();

    const int gid = blockIdx.x * 128 + tid;      // 32768 pairs
    const int b = gid >> 11;
    const int n = (gid & 2047) << 1;             // even pixel

    float2 qa[8], ka[8], va[64];
#pragma unroll
    for (int i = 0; i < 8; i++) {
        qa[i] = make_float2(qbs[i], qbs[i]);
        ka[i] = make_float2(kbs[i], kbs[i]);
    }
#pragma unroll
    for (int j = 0; j < 64; j++) va[j] = make_float2(vbs[j], vbs[j]);

    const float* fp = f + (size_t)b * CC * HWN + n;
#pragma unroll 4
    for (int c = 0; c < 64; c++) {
        const float2 fv = *(const float2*)(fp + (size_t)c * HWN);
#pragma unroll
        for (int i = 0; i < 8; i++) {
            const float wq = qws[i*64 + c], wk = kws[i*64 + c];
            qa[i].x += wq * fv.x; qa[i].y += wq * fv.y;
            ka[i].x += wk * fv.x; ka[i].y += wk * fv.y;
        }
#pragma unroll
        for (int j = 0; j < 64; j++) {
            const float wv = vws[j*64 + c];
            va[j].x += wv * fv.x; va[j].y += wv * fv.y;
        }
    }
    const float ss = 0.51006975f;   // log2(e)/sqrt(8)
    uint4 u;
    u.x = pack2(qa[0].x*ss, qa[1].x*ss); u.y = pack2(qa[2].x*ss, qa[3].x*ss);
    u.z = pack2(qa[4].x*ss, qa[5].x*ss); u.w = pack2(qa[6].x*ss, qa[7].x*ss);
    ((uint4*)g_q)[b*HWN + n] = u;
    u.x = pack2(qa[0].y*ss, qa[1].y*ss); u.y = pack2(qa[2].y*ss, qa[3].y*ss);
    u.z = pack2(qa[4].y*ss, qa[5].y*ss); u.w = pack2(qa[6].y*ss, qa[7].y*ss);
    ((uint4*)g_q)[b*HWN + n + 1] = u;
    u.x = pack2(ka[0].x, ka[1].x); u.y = pack2(ka[2].x, ka[3].x);
    u.z = pack2(ka[4].x, ka[5].x); u.w = pack2(ka[6].x, ka[7].x);
    ((uint4*)g_k)[b*HWN + n] = u;
    u.x = pack2(ka[0].y, ka[1].y); u.y = pack2(ka[2].y, ka[3].y);
    u.z = pack2(ka[4].y, ka[5].y); u.w = pack2(ka[6].y, ka[7].y);
    ((uint4*)g_k)[b*HWN + n + 1] = u;
#pragma unroll
    for (int c = 0; c < 64; c++) {
        const unsigned h2 = pack2(va[c].x, va[c].y);
        *(unsigned*)(g_v + ((size_t)(b*CC + c))*HWN + n) = h2;
    }
}

// ---------------------------------------------------------------------------
// Flash-fused attention + conv_o + residual (fp16 mma, P in regs, cp.async V).
// EXACT R8 version (proven 200.6us) — no pipeline, no K prefetch.
// ---------------------------------------------------------------------------
#define VROWB   272
#define VBUFB   (64*VROWB)
#define PS_STRIDE 132
#define OW_S    68
#define SM_OWS  8448
#define SM_DEN  (SM_OWS + 64*OW_S)
#define ATTN_SMEM_FLOATS (SM_DEN + 128)
#define ATTN_SMEM_BYTES  (ATTN_SMEM_FLOATS * 4)

__global__ void __launch_bounds__(256, 2) attn_kernel(
    const float* __restrict__ feat,
    const float* __restrict__ ow, const float* __restrict__ ob,
    const float* __restrict__ scale, float* __restrict__ ctx)
{
    extern __shared__ float sm[];
    char* smc = (char*)sm;
    float* den = sm + SM_DEN;

    const int b   = blockIdx.x >> 5;
    const int q0  = (blockIdx.x & 31) * 128;
    const int tid = threadIdx.x;
    const int w   = tid >> 5;
    const int lane = tid & 31;
    const int g   = lane >> 2;
    const int t4  = lane & 3;

    const int qrow = q0 + w*16 + g;
    const unsigned qa0 = g_q[(b*HWN + qrow)*4 + t4];
    const unsigned qa1 = g_q[(b*HWN + qrow + 8)*4 + t4];

    float o[8][4];
#pragma unroll
    for (int i = 0; i < 8; i++)
#pragma unroll
        for (int j = 0; j < 4; j++) o[i][j] = 0.f;
    float dsum0 = 0.f, dsum1 = 0.f;

    const int vc  = tid >> 2;
    const int seg = tid & 3;
    const char* gv_src = (const char*)g_v
        + 2*(((size_t)(b*CC + vc))*HWN + seg*32);
    const unsigned vdst = su32(smc) + vc*VROWB + seg*64;

    const int lm_m = lane >> 3, lm_r = lane & 7;
    const unsigned lm_base = su32(smc)
        + ((lm_m >> 1)*8 + lm_r)*VROWB + (lm_m & 1)*16;

    {
        const char* s = gv_src;
#pragma unroll
        for (int i = 0; i < 4; i++) CP_ASYNC16(vdst + i*16, s + i*16);
        CP_COMMIT();
    }

    const unsigned* gk = g_k;
    for (int kt = 0; kt < 32; kt++) {
        const int k0 = kt * 128;
        CP_WAIT0();
        __syncthreads();

        if (kt < 31) {
            const char* s = gv_src + 2*(size_t)(k0 + 128);
            const unsigned d = vdst + ((kt + 1) & 1) * VBUFB;
#pragma unroll
            for (int i = 0; i < 4; i++) CP_ASYNC16(d + i*16, s + i*16);
            CP_COMMIT();
        }

        unsigned kf[16];
#pragma unroll
        for (int i = 0; i < 16; i++)
            kf[i] = gk[(b*HWN + k0 + 8*i + g)*4 + t4];

        const unsigned bufoff = (kt & 1) * VBUFB;
        unsigned h2s0 = 0, h2s1 = 0;

#pragma unroll
        for (int kb = 0; kb < 8; kb++) {
            float s0=0.f,s1=0.f,s2=0.f,s3=0.f,s4=0.f,s5=0.f,s6=0.f,s7=0.f;
            mma_f16_k8(s0,s1,s2,s3, qa0,qa1, kf[2*kb]);
            mma_f16_k8(s4,s5,s6,s7, qa0,qa1, kf[2*kb+1]);
            const unsigned a0 = ex2_h2(cvt_h2(s0, s1));
            const unsigned a1 = ex2_h2(cvt_h2(s2, s3));
            const unsigned a2 = ex2_h2(cvt_h2(s4, s5));
            const unsigned a3 = ex2_h2(cvt_h2(s6, s7));
            h2s0 = hadd2u(h2s0, hadd2u(a0, a2));
            h2s1 = hadd2u(h2s1, hadd2u(a1, a3));
#pragma unroll
            for (int cbp = 0; cbp < 4; cbp++) {
                unsigned v0, v1, v2, v3;
                ldsm_x4(v0, v1, v2, v3,
                        lm_base + bufoff + cbp*(16*VROWB) + kb*32);
                mma_f16_k16(o[2*cbp],     a0,a1,a2,a3, v0, v1);
                mma_f16_k16(o[2*cbp + 1], a0,a1,a2,a3, v2, v3);
            }
        }
        const __half2 hh0 = *(__half2*)&h2s0;
        const __half2 hh1 = *(__half2*)&h2s1;
        const float2 f0 = __half22float2(hh0);
        const float2 f1 = __half22float2(hh1);
        dsum0 += f0.x + f0.y;
        dsum1 += f1.x + f1.y;
    }
    __syncthreads();

    dsum0 += __shfl_xor_sync(0xffffffffu, dsum0, 1);
    dsum0 += __shfl_xor_sync(0xffffffffu, dsum0, 2);
    dsum1 += __shfl_xor_sync(0xffffffffu, dsum1, 1);
    dsum1 += __shfl_xor_sync(0xffffffffu, dsum1, 2);
    if (t4 == 0) {
        den[w*16 + g]     = dsum0;
        den[w*16 + 8 + g] = dsum1;
    }

    float* attS = sm;
#pragma unroll
    for (int cb = 0; cb < 8; cb++) {
        const int cA = cb*8 + 2*t4;
        const int ql = w*16 + g;
        attS[cA*PS_STRIDE + ql]           = o[cb][0];
        attS[(cA+1)*PS_STRIDE + ql]       = o[cb][1];
        attS[cA*PS_STRIDE + ql + 8]       = o[cb][2];
        attS[(cA+1)*PS_STRIDE + ql + 8]   = o[cb][3];
    }
    float* owS = sm + SM_OWS;
#pragma unroll
    for (int i = 0; i < 16; i++) {
        const int idx = tid + i*256;
        owS[(idx & 63)*OW_S + (idx >> 6)] = ow[idx];
    }
    __syncthreads();

    const int oy = tid >> 5;
    const int qx = tid & 31;
    const float4 dv = *(const float4*)&den[qx*4];
    const float rd[4] = {1.f/dv.x, 1.f/dv.y, 1.f/dv.z, 1.f/dv.w};

    float oacc[8][4];
#pragma unroll
    for (int i = 0; i < 8; i++)
#pragma unroll
        for (int j = 0; j < 4; j++) oacc[i][j] = 0.f;

#pragma unroll 4
    for (int c = 0; c < 64; c++) {
        const float4 av = *(const float4*)&attS[c*PS_STRIDE + qx*4];
        const float4 w0 = *(const float4*)&owS[c*OW_S + oy*8];
        const float4 w1 = *(const float4*)&owS[c*OW_S + oy*8 + 4];
        const float wv[8] = {w0.x, w0.y, w0.z, w0.w, w1.x, w1.y, w1.z, w1.w};
#pragma unroll
        for (int i = 0; i < 8; i++) {
            oacc[i][0] += wv[i] * av.x;
            oacc[i][1] += wv[i] * av.y;
            oacc[i][2] += wv[i] * av.z;
            oacc[i][3] += wv[i] * av.w;
        }
    }
    const float sc = scale[0];
#pragma unroll
    for (int i = 0; i < 8; i++) {
        const int oc = oy*8 + i;
        const float obv = __ldg(&ob[oc]);
        const size_t base = ((size_t)(b*CC + oc)) * HWN + q0 + qx*4;
        const float4 f4 = *(const float4*)&feat[base];
        float4 r;
        r.x = f4.x + sc * (oacc[i][0]*rd[0] + obv);
        r.y = f4.y + sc * (oacc[i][1]*rd[1] + obv);
        r.z = f4.z + sc * (oacc[i][2]*rd[2] + obv);
        r.w = f4.w + sc * (oacc[i][3]*rd[3] + obv);
        *(float4*)&ctx[base] = r;
    }
}

// ---------------------------------------------------------------------------
// pool 64x64 -> 8x8 (one output per thread, 65536 threads)
// ---------------------------------------------------------------------------
__global__ void pool1_kernel(const float* __restrict__ ctx)
{
    const int gid = blockIdx.x * 256 + threadIdx.x;
    const int pix = gid & 63;
    const int ox = pix & 7, oy = pix >> 3;
    const int bc = gid >> 6;
    const float4* src = (const float4*)(ctx + (size_t)bc * HWN + oy*8*64 + ox*8);
    float s = 0.f;
#pragma unroll
    for (int r = 0; r < 8; r++) {
        const float4 a = src[r*16];
        const float4 c = src[r*16 + 1];
        s += (a.x + a.y + a.z + a.w) + (c.x + c.y + c.z + c.w);
    }
    g_p1[gid] = s * (1.f/64.f);
}

// ---------------------------------------------------------------------------
// conv1 3x3 SAME on 8x8, 64->128, bn, relu. padded 10x10 input.
// ---------------------------------------------------------------------------
__global__ void __launch_bounds__(128) conv1_kernel(
    const float* __restrict__ w, const float* __restrict__ bias,
    const float* __restrict__ bg, const float* __restrict__ bb,
    const float* __restrict__ bm, const float* __restrict__ bv)
{
    __shared__ float insp[64*100];
    __shared__ float ws[8*576];
    const int tid = threadIdx.x;
    const int b  = blockIdx.x >> 4;
    const int og = (blockIdx.x & 15) * 8;

    for (int i = tid; i < 6400; i += 128) insp[i] = 0.f;
    __syncthreads();
    for (int i = tid; i < 4096; i += 128) {
        const int ic = i >> 6, pix = i & 63;
        insp[ic*100 + ((pix >> 3) + 1)*10 + (pix & 7) + 1] = g_p1[b*4096 + i];
    }
    for (int i = tid; i < 4608; i += 128) ws[i] = w[og*576 + i];
    __syncthreads();

    const int ol   = tid >> 4;
    const int o    = og + ol;
    const int quad = tid & 15;
    const int y    = quad >> 1;
    const int xh   = (quad & 1) * 4;

    float acc[4] = {0.f, 0.f, 0.f, 0.f};
    const float* wp0 = ws + ol*576;
    const float* ip0 = insp + y*10 + xh;
    for (int ic = 0; ic < 64; ic++) {
        const float* wp = wp0 + ic*9;
        const float* ip = ip0 + ic*100;
        float w0 = wp[0], w1 = wp[1], w2 = wp[2];
        float w3 = wp[3], w4 = wp[4], w5 = wp[5];
        float w6 = wp[6], w7 = wp[7], w8 = wp[8];
        float r0[6], r1[6], r2[6];
#pragma unroll
        for (int j = 0; j < 6; j++) {
            r0[j] = ip[j]; r1[j] = ip[10 + j]; r2[j] = ip[20 + j];
        }
#pragma unroll
        for (int j = 0; j < 4; j++) {
            acc[j] += w0*r0[j] + w1*r0[j+1] + w2*r0[j+2]
                    + w3*r1[j] + w4*r1[j+1] + w5*r1[j+2]
                    + w6*r2[j] + w7*r2[j+1] + w8*r2[j+2];
        }
    }
    const float inv = bg[o] * rsqrtf(bv[o] + 1e-5f);
    const float sh  = bb[o] - bm[o]*inv;
    const float bo  = bias[o];
    float* dst = g_c1 + b*8192 + o*64 + y*8 + xh;
#pragma unroll
    for (int j = 0; j < 4; j++)
        dst[j] = fmaxf((acc[j] + bo)*inv + sh, 0.f);
}

// ---------------------------------------------------------------------------
// conv2 (with fused 8x8->4x4 pool) 3x3 SAME on 4x4, 128->256, bn, relu.
// Branch-free padded 6x6 input (stride 8); thread = (o, output row), 4 px.
// block = (b, og32): 32 o x 4 rows = 128 threads; grid 128.
// ---------------------------------------------------------------------------
__global__ void __launch_bounds__(128) conv2_kernel(
    const float* __restrict__ w, const float* __restrict__ bias,
    const float* __restrict__ bg, const float* __restrict__ bb,
    const float* __restrict__ bm, const float* __restrict__ bv)
{
    __shared__ float insp[128*48];       // [ic][6 rows x 8 stride], zero-padded
    const int tid = threadIdx.x;
    const int b  = blockIdx.x >> 3;
    const int og = (blockIdx.x & 7) * 32;

    for (int i = tid; i < 6144; i += 128) insp[i] = 0.f;
    __syncthreads();
    // pooled fill: g_c1 8x8 -> 4x4 averages, into padded interior [1..4][1..4]
    for (int i = tid; i < 2048; i += 128) {
        const int ic = i >> 4, pix = i & 15;
        const int py = pix >> 2, px = pix & 3;
        const float* src = g_c1 + (size_t)(b*128 + ic)*64 + (py*2)*8 + px*2;
        insp[ic*48 + (py + 1)*8 + px + 1] =
            (src[0] + src[1] + src[8] + src[9]) * 0.25f;
    }
    __syncthreads();

    const int ol = tid >> 2;            // 0..31
    const int o  = og + ol;
    const int y  = tid & 3;             // output row

    float acc[4] = {0.f, 0.f, 0.f, 0.f};
    const float* ip0 = insp + y*8;      // padded rows y, y+1, y+2
    const float* wpo = w + (size_t)o*128*9;
    for (int ic = 0; ic < 128; ic++) {
        const float* wp = wpo + ic*9;
        const float* ip = ip0 + ic*48;
        const float w0 = __ldg(wp),   w1 = __ldg(wp+1), w2 = __ldg(wp+2);
        const float w3 = __ldg(wp+3), w4 = __ldg(wp+4), w5 = __ldg(wp+5);
        const float w6 = __ldg(wp+6), w7 = __ldg(wp+7), w8 = __ldg(wp+8);
        float r0[6], r1[6], r2[6];
#pragma unroll
        for (int j = 0; j < 6; j++) {
            r0[j] = ip[j]; r1[j] = ip[8 + j]; r2[j] = ip[16 + j];
        }
#pragma unroll
        for (int j = 0; j < 4; j++) {
            acc[j] += w0*r0[j] + w1*r0[j+1] + w2*r0[j+2]
                    + w3*r1[j] + w4*r1[j+1] + w5*r1[j+2]
                    + w6*r2[j] + w7*r2[j+1] + w8*r2[j+2];
        }
    }
    const float inv = bg[o] * rsqrtf(bv[o] + 1e-5f);
    const float sh  = bb[o] - bm[o]*inv;
    const float bo  = bias[o];
    float* dst = g_c2 + b*4096 + o*16 + y*4;
#pragma unroll
    for (int j = 0; j < 4; j++)
        dst[j] = fmaxf((acc[j] + bo)*inv + sh, 0.f);
}

// gfeat + hierarchical heads.  block per batch.
__global__ void head_kernel(
    const float* __restrict__ w1, const float* __restrict__ b1,
    const float* __restrict__ w2, const float* __restrict__ b2,
    float* __restrict__ out)
{
    __shared__ float gfs[256];
    __shared__ float l1s[6], p1s[6], l2s[6];
    const int b = blockIdx.x, t = threadIdx.x;

    const float* p = g_c2 + b*4096 + t*16;
    float s = 0.f;
#pragma unroll
    for (int i = 0; i < 16; i++) s += p[i];
    s *= (1.f/16.f);
    gfs[t] = s;
    out[OUT_GF + b*256 + t] = s;
    __syncthreads();

    if (t < 6) {
        float a = b1[t];
        for (int c = 0; c < 256; c++) a += gfs[c] * w1[t*256 + c];
        l1s[t] = a;
        out[OUT_L1 + b*6 + t] = a;
    }
    __syncthreads();
    if (t == 0) {
        float mx = l1s[0];
#pragma unroll
        for (int i = 1; i < 6; i++) mx = fmaxf(mx, l1s[i]);
        float se = 0.f, e[6];
#pragma unroll
        for (int i = 0; i < 6; i++) { e[i] = __expf(l1s[i] - mx); se += e[i]; }
        const float rse = 1.f / se;
#pragma unroll
        for (int i = 0; i < 6; i++) {
            p1s[i] = e[i] * rse;
            out[OUT_P1 + b*6 + i] = p1s[i];
        }
    }
    __syncthreads();
    if (t < 6) {
        float a = b2[t];
        for (int c = 0; c < 256; c++) a += gfs[c] * w2[t*262 + c];
#pragma unroll
        for (int j = 0; j < 6; j++) a += p1s[j] * w2[t*262 + 256 + j];
        l2s[t] = a;
        out[OUT_L2 + b*6 + t] = a;
    }
    __syncthreads();
    if (t == 0) {
        float mx = l2s[0];
#pragma unroll
        for (int i = 1; i < 6; i++) mx = fmaxf(mx, l2s[i]);
        float se = 0.f, e[6];
#pragma unroll
        for (int i = 0; i < 6; i++) { e[i] = __expf(l2s[i] - mx); se += e[i]; }
        const float rse = 1.f / se;
#pragma unroll
        for (int i = 0; i < 6; i++) out[OUT_P2 + b*6 + i] = e[i] * rse;
    }
}

// ---------------------------------------------------------------------------
extern "C" void kernel_launch(void* const* d_in, const int* in_sizes, int n_in,
                              void* d_out, int out_size)
{
    (void)in_sizes; (void)n_in; (void)out_size;
    const float* feat = (const float*)d_in[0];
    const float* qw = (const float*)d_in[1];
    const float* qb = (const float*)d_in[2];
    const float* kw = (const float*)d_in[3];
    const float* kb = (const float*)d_in[4];
    const float* vw = (const float*)d_in[5];
    const float* vb = (const float*)d_in[6];
    const float* ow = (const float*)d_in[7];
    const float* ob = (const float*)d_in[8];
    const float* sc = (const float*)d_in[9];
    const float* c1w = (const float*)d_in[10];
    const float* c1b = (const float*)d_in[11];
    const float* bg1 = (const float*)d_in[12];
    const float* bb1 = (const float*)d_in[13];
    const float* bm1 = (const float*)d_in[14];
    const float* bv1 = (const float*)d_in[15];
    const float* c2w = (const float*)d_in[16];
    const float* c2b = (const float*)d_in[17];
    const float* bg2 = (const float*)d_in[18];
    const float* bb2 = (const float*)d_in[19];
    const float* bm2 = (const float*)d_in[20];
    const float* bv2 = (const float*)d_in[21];
    const float* w1 = (const float*)d_in[22];
    const float* b1 = (const float*)d_in[23];
    const float* w2 = (const float*)d_in[24];
    const float* b2 = (const float*)d_in[25];

    float* out = (float*)d_out;
    float* ctx = out + OUT_CTX;

    cudaFuncSetAttribute(attn_kernel,
                         cudaFuncAttributeMaxDynamicSharedMemorySize,
                         ATTN_SMEM_BYTES);

    qkv_kernel<<<256, 128>>>(feat, qw, qb, kw, kb, vw, vb);
    nop_kernel<<<1, 32>>>();
    nop_kernel<<<1, 32>>>();
    attn_kernel<<<512, 256, ATTN_SMEM_BYTES>>>(feat, ow, ob, sc, ctx);
    pool1_kernel<<<256, 256>>>(ctx);
    conv1_kernel<<<256, 128>>>(c1w, c1b, bg1, bb1, bm1, bv1);
    conv2_kernel<<<128, 128>>>(c2w, c2b, bg2, bb2, bm2, bv2);
    head_kernel<<<16, 256>>>(w1, b1, w2, b2, out);
}

// round 13
// speedup vs baseline: 1.0851x; 1.0071x over previous
#include <cuda_runtime.h>
#include <cuda_fp16.h>
#include <math.h>

#define BB 16
#define CC 64
#define HWN 4096

// output layout (floats): l1,l2,p1,p2,gfeat,context
#define OUT_L1 0
#define OUT_L2 96
#define OUT_P1 192
#define OUT_P2 288
#define OUT_GF 384
#define OUT_CTX 4480

// scratch (device globals: no allocations allowed)
__device__ unsigned g_q[BB*HWN*4];     // half2 [b][n][d/2], pre-scaled by log2e/sqrt(8)
__device__ unsigned g_k[BB*HWN*4];     // half2 [b][n][d/2]
__device__ __half   g_v[BB*CC*HWN];    // half  [b][c][n]
__device__ float g_p1[BB*CC*64];       // pooled 8x8
__device__ float g_c1[BB*128*64];      // conv1 out 8x8
__device__ float g_c2[BB*256*16];      // conv2 out 4x4

// fp16-accumulator QK mma: D (f16x2 x2) = A(16x8) * B(8x8), C = 0
__device__ __forceinline__ void mma_f16_k8_h(
    unsigned& d0, unsigned& d1,
    unsigned a0, unsigned a1, unsigned b0)
{
    asm volatile(
        "mma.sync.aligned.m16n8k8.row.col.f16.f16.f16.f16 "
        "{%0,%1}, {%2,%3}, {%4}, {%5,%5};\n"
        : "=r"(d0), "=r"(d1)
        : "r"(a0), "r"(a1), "r"(b0), "r"(0u));
}

__device__ __forceinline__ void mma_f16_k16(
    float* d,
    unsigned a0, unsigned a1, unsigned a2, unsigned a3,
    unsigned b0, unsigned b1)
{
    asm volatile(
        "mma.sync.aligned.m16n8k16.row.col.f32.f16.f16.f32 "
        "{%0,%1,%2,%3}, {%4,%5,%6,%7}, {%8,%9}, {%0,%1,%2,%3};\n"
        : "+f"(d[0]), "+f"(d[1]), "+f"(d[2]), "+f"(d[3])
        : "r"(a0), "r"(a1), "r"(a2), "r"(a3), "r"(b0), "r"(b1));
}

__device__ __forceinline__ unsigned pack2(float lo, float hi) {
    __half2 h = __floats2half2_rn(lo, hi);
    return reinterpret_cast<unsigned&>(h);
}
__device__ __forceinline__ unsigned ex2_h2(unsigned x) {
    unsigned r;
    asm("ex2.approx.f16x2 %0, %1;" : "=r"(r) : "r"(x));
    return r;
}
__device__ __forceinline__ unsigned hadd2u(unsigned a, unsigned b) {
    unsigned r;
    asm("add.f16x2 %0, %1, %2;" : "=r"(r) : "r"(a), "r"(b));
    return r;
}
__device__ __forceinline__ void ldsm_x4(
    unsigned& r0, unsigned& r1, unsigned& r2, unsigned& r3, unsigned addr)
{
    asm volatile("ldmatrix.sync.aligned.m8n8.x4.shared.b16 {%0,%1,%2,%3}, [%4];"
                 : "=r"(r0), "=r"(r1), "=r"(r2), "=r"(r3) : "r"(addr));
}
__device__ __forceinline__ unsigned su32(const void* p) {
    return (unsigned)__cvta_generic_to_shared(p);
}
#define CP_ASYNC16(dst, src) \
    asm volatile("cp.async.cg.shared.global [%0], [%1], 16;" :: "r"(dst), "l"(src))
#define CP_COMMIT() asm volatile("cp.async.commit_group;")
#define CP_WAIT0()  asm volatile("cp.async.wait_group 0;" ::: "memory")

// QK (fp16-acc) + exp for one n16 block; accumulates fp16 denominator partials.
// f16 D frag of the two k8 mmas == PV A-frag halves directly (no cvt needed).
__device__ __forceinline__ void qk_exp(
    const unsigned* kf, int kb, unsigned qa0, unsigned qa1,
    unsigned* a, unsigned& h2s0, unsigned& h2s1)
{
    unsigned p0, p1, p2, p3;
    mma_f16_k8_h(p0, p1, qa0, qa1, kf[2*kb]);
    mma_f16_k8_h(p2, p3, qa0, qa1, kf[2*kb+1]);
    a[0] = ex2_h2(p0);
    a[1] = ex2_h2(p1);
    a[2] = ex2_h2(p2);
    a[3] = ex2_h2(p3);
    h2s0 = hadd2u(h2s0, hadd2u(a[0], a[2]));
    h2s1 = hadd2u(h2s1, hadd2u(a[1], a[3]));
}

// ---------------------------------------------------------------------------
// nop spacer kernels (profiler alignment: attn at launch position 4)
// ---------------------------------------------------------------------------
__global__ void nop_kernel() {}

// ---------------------------------------------------------------------------
// QKV: fused 1x1 convs. thread = (b, 2 adjacent pixels). Outputs fp16.
// ---------------------------------------------------------------------------
__global__ void __launch_bounds__(128) qkv_kernel(
    const float* __restrict__ f,
    const float* __restrict__ qw, const float* __restrict__ qb,
    const float* __restrict__ kw, const float* __restrict__ kb,
    const float* __restrict__ vw, const float* __restrict__ vb)
{
    __shared__ float qws[512], kws[512], vws[4096];
    __shared__ float qbs[8], kbs[8], vbs[64];
    const int tid = threadIdx.x;
    for (int i = tid; i < 512; i += 128) { qws[i] = qw[i]; kws[i] = kw[i]; }
    for (int i = tid; i < 4096; i += 128) vws[i] = vw[i];
    if (tid < 8)  { qbs[tid] = qb[tid]; kbs[tid] = kb[tid]; }
    if (tid < 64) vbs[tid] = vb[tid];
    __syncthreads();

    const int gid = blockIdx.x * 128 + tid;      // 32768 pairs
    const int b = gid >> 11;
    const int n = (gid & 2047) << 1;             // even pixel

    float2 qa[8], ka[8], va[64];
#pragma unroll
    for (int i = 0; i < 8; i++) {
        qa[i] = make_float2(qbs[i], qbs[i]);
        ka[i] = make_float2(kbs[i], kbs[i]);
    }
#pragma unroll
    for (int j = 0; j < 64; j++) va[j] = make_float2(vbs[j], vbs[j]);

    const float* fp = f + (size_t)b * CC * HWN + n;
#pragma unroll 4
    for (int c = 0; c < 64; c++) {
        const float2 fv = *(const float2*)(fp + (size_t)c * HWN);
#pragma unroll
        for (int i = 0; i < 8; i++) {
            const float wq = qws[i*64 + c], wk = kws[i*64 + c];
            qa[i].x += wq * fv.x; qa[i].y += wq * fv.y;
            ka[i].x += wk * fv.x; ka[i].y += wk * fv.y;
        }
#pragma unroll
        for (int j = 0; j < 64; j++) {
            const float wv = vws[j*64 + c];
            va[j].x += wv * fv.x; va[j].y += wv * fv.y;
        }
    }
    const float ss = 0.51006975f;   // log2(e)/sqrt(8)
    uint4 u;
    u.x = pack2(qa[0].x*ss, qa[1].x*ss); u.y = pack2(qa[2].x*ss, qa[3].x*ss);
    u.z = pack2(qa[4].x*ss, qa[5].x*ss); u.w = pack2(qa[6].x*ss, qa[7].x*ss);
    ((uint4*)g_q)[b*HWN + n] = u;
    u.x = pack2(qa[0].y*ss, qa[1].y*ss); u.y = pack2(qa[2].y*ss, qa[3].y*ss);
    u.z = pack2(qa[4].y*ss, qa[5].y*ss); u.w = pack2(qa[6].y*ss, qa[7].y*ss);
    ((uint4*)g_q)[b*HWN + n + 1] = u;
    u.x = pack2(ka[0].x, ka[1].x); u.y = pack2(ka[2].x, ka[3].x);
    u.z = pack2(ka[4].x, ka[5].x); u.w = pack2(ka[6].x, ka[7].x);
    ((uint4*)g_k)[b*HWN + n] = u;
    u.x = pack2(ka[0].y, ka[1].y); u.y = pack2(ka[2].y, ka[3].y);
    u.z = pack2(ka[4].y, ka[5].y); u.w = pack2(ka[6].y, ka[7].y);
    ((uint4*)g_k)[b*HWN + n + 1] = u;
#pragma unroll
    for (int c = 0; c < 64; c++) {
        const unsigned h2 = pack2(va[c].x, va[c].y);
        *(unsigned*)(g_v + ((size_t)(b*CC + c))*HWN + n) = h2;
    }
}

// ---------------------------------------------------------------------------
// Flash-fused attention + conv_o + residual (fp16 mma, P in regs, cp.async V).
// R13: fp16-acc QK (no cvt; D frag == PV A frag) + exp/PV software pipeline.
// ---------------------------------------------------------------------------
#define VROWB   272
#define VBUFB   (64*VROWB)
#define PS_STRIDE 132
#define OW_S    68
#define SM_OWS  8448
#define SM_DEN  (SM_OWS + 64*OW_S)
#define ATTN_SMEM_FLOATS (SM_DEN + 128)
#define ATTN_SMEM_BYTES  (ATTN_SMEM_FLOATS * 4)

__global__ void __launch_bounds__(256, 2) attn_kernel(
    const float* __restrict__ feat,
    const float* __restrict__ ow, const float* __restrict__ ob,
    const float* __restrict__ scale, float* __restrict__ ctx)
{
    extern __shared__ float sm[];
    char* smc = (char*)sm;
    float* den = sm + SM_DEN;

    const int b   = blockIdx.x >> 5;
    const int q0  = (blockIdx.x & 31) * 128;
    const int tid = threadIdx.x;
    const int w   = tid >> 5;
    const int lane = tid & 31;
    const int g   = lane >> 2;
    const int t4  = lane & 3;

    const int qrow = q0 + w*16 + g;
    const unsigned qa0 = g_q[(b*HWN + qrow)*4 + t4];
    const unsigned qa1 = g_q[(b*HWN + qrow + 8)*4 + t4];

    float o[8][4];
#pragma unroll
    for (int i = 0; i < 8; i++)
#pragma unroll
        for (int j = 0; j < 4; j++) o[i][j] = 0.f;
    float dsum0 = 0.f, dsum1 = 0.f;

    const int vc  = tid >> 2;
    const int seg = tid & 3;
    const char* gv_src = (const char*)g_v
        + 2*(((size_t)(b*CC + vc))*HWN + seg*32);
    const unsigned vdst = su32(smc) + vc*VROWB + seg*64;

    const int lm_m = lane >> 3, lm_r = lane & 7;
    const unsigned lm_base = su32(smc)
        + ((lm_m >> 1)*8 + lm_r)*VROWB + (lm_m & 1)*16;

    {
        const char* s = gv_src;
#pragma unroll
        for (int i = 0; i < 4; i++) CP_ASYNC16(vdst + i*16, s + i*16);
        CP_COMMIT();
    }

    const unsigned* gk = g_k;
    for (int kt = 0; kt < 32; kt++) {
        const int k0 = kt * 128;
        CP_WAIT0();
        __syncthreads();

        if (kt < 31) {
            const char* s = gv_src + 2*(size_t)(k0 + 128);
            const unsigned d = vdst + ((kt + 1) & 1) * VBUFB;
#pragma unroll
            for (int i = 0; i < 4; i++) CP_ASYNC16(d + i*16, s + i*16);
            CP_COMMIT();
        }

        unsigned kf[16];
#pragma unroll
        for (int i = 0; i < 16; i++)
            kf[i] = gk[(b*HWN + k0 + 8*i + g)*4 + t4];

        const unsigned bufoff = (kt & 1) * VBUFB;
        unsigned h2s0 = 0, h2s1 = 0;

        // software pipeline: exp(kb+1) overlaps PV(kb)
        unsigned acur[4], anext[4];
        qk_exp(kf, 0, qa0, qa1, acur, h2s0, h2s1);
#pragma unroll
        for (int kb = 0; kb < 8; kb++) {
            if (kb < 7) qk_exp(kf, kb + 1, qa0, qa1, anext, h2s0, h2s1);
#pragma unroll
            for (int cbp = 0; cbp < 4; cbp++) {
                unsigned v0, v1, v2, v3;
                ldsm_x4(v0, v1, v2, v3,
                        lm_base + bufoff + cbp*(16*VROWB) + kb*32);
                mma_f16_k16(o[2*cbp],     acur[0],acur[1],acur[2],acur[3], v0, v1);
                mma_f16_k16(o[2*cbp + 1], acur[0],acur[1],acur[2],acur[3], v2, v3);
            }
            if (kb < 7) {
#pragma unroll
                for (int j = 0; j < 4; j++) acur[j] = anext[j];
            }
        }

        const __half2 hh0 = *(__half2*)&h2s0;
        const __half2 hh1 = *(__half2*)&h2s1;
        const float2 f0 = __half22float2(hh0);
        const float2 f1 = __half22float2(hh1);
        dsum0 += f0.x + f0.y;
        dsum1 += f1.x + f1.y;
    }
    __syncthreads();

    dsum0 += __shfl_xor_sync(0xffffffffu, dsum0, 1);
    dsum0 += __shfl_xor_sync(0xffffffffu, dsum0, 2);
    dsum1 += __shfl_xor_sync(0xffffffffu, dsum1, 1);
    dsum1 += __shfl_xor_sync(0xffffffffu, dsum1, 2);
    if (t4 == 0) {
        den[w*16 + g]     = dsum0;
        den[w*16 + 8 + g] = dsum1;
    }

    float* attS = sm;
#pragma unroll
    for (int cb = 0; cb < 8; cb++) {
        const int cA = cb*8 + 2*t4;
        const int ql = w*16 + g;
        attS[cA*PS_STRIDE + ql]           = o[cb][0];
        attS[(cA+1)*PS_STRIDE + ql]       = o[cb][1];
        attS[cA*PS_STRIDE + ql + 8]       = o[cb][2];
        attS[(cA+1)*PS_STRIDE + ql + 8]   = o[cb][3];
    }
    float* owS = sm + SM_OWS;
#pragma unroll
    for (int i = 0; i < 16; i++) {
        const int idx = tid + i*256;
        owS[(idx & 63)*OW_S + (idx >> 6)] = ow[idx];
    }
    __syncthreads();

    const int oy = tid >> 5;
    const int qx = tid & 31;
    const float4 dv = *(const float4*)&den[qx*4];
    const float rd[4] = {1.f/dv.x, 1.f/dv.y, 1.f/dv.z, 1.f/dv.w};

    float oacc[8][4];
#pragma unroll
    for (int i = 0; i < 8; i++)
#pragma unroll
        for (int j = 0; j < 4; j++) oacc[i][j] = 0.f;

#pragma unroll 4
    for (int c = 0; c < 64; c++) {
        const float4 av = *(const float4*)&attS[c*PS_STRIDE + qx*4];
        const float4 w0 = *(const float4*)&owS[c*OW_S + oy*8];
        const float4 w1 = *(const float4*)&owS[c*OW_S + oy*8 + 4];
        const float wv[8] = {w0.x, w0.y, w0.z, w0.w, w1.x, w1.y, w1.z, w1.w};
#pragma unroll
        for (int i = 0; i < 8; i++) {
            oacc[i][0] += wv[i] * av.x;
            oacc[i][1] += wv[i] * av.y;
            oacc[i][2] += wv[i] * av.z;
            oacc[i][3] += wv[i] * av.w;
        }
    }
    const float sc = scale[0];
#pragma unroll
    for (int i = 0; i < 8; i++) {
        const int oc = oy*8 + i;
        const float obv = __ldg(&ob[oc]);
        const size_t base = ((size_t)(b*CC + oc)) * HWN + q0 + qx*4;
        const float4 f4 = *(const float4*)&feat[base];
        float4 r;
        r.x = f4.x + sc * (oacc[i][0]*rd[0] + obv);
        r.y = f4.y + sc * (oacc[i][1]*rd[1] + obv);
        r.z = f4.z + sc * (oacc[i][2]*rd[2] + obv);
        r.w = f4.w + sc * (oacc[i][3]*rd[3] + obv);
        *(float4*)&ctx[base] = r;
    }
}

// ---------------------------------------------------------------------------
// pool 64x64 -> 8x8 (one output per thread, 65536 threads)
// ---------------------------------------------------------------------------
__global__ void pool1_kernel(const float* __restrict__ ctx)
{
    const int gid = blockIdx.x * 256 + threadIdx.x;
    const int pix = gid & 63;
    const int ox = pix & 7, oy = pix >> 3;
    const int bc = gid >> 6;
    const float4* src = (const float4*)(ctx + (size_t)bc * HWN + oy*8*64 + ox*8);
    float s = 0.f;
#pragma unroll
    for (int r = 0; r < 8; r++) {
        const float4 a = src[r*16];
        const float4 c = src[r*16 + 1];
        s += (a.x + a.y + a.z + a.w) + (c.x + c.y + c.z + c.w);
    }
    g_p1[gid] = s * (1.f/64.f);
}

// ---------------------------------------------------------------------------
// conv1 3x3 SAME on 8x8, 64->128, bn, relu. padded 10x10 input.
// ---------------------------------------------------------------------------
__global__ void __launch_bounds__(128) conv1_kernel(
    const float* __restrict__ w, const float* __restrict__ bias,
    const float* __restrict__ bg, const float* __restrict__ bb,
    const float* __restrict__ bm, const float* __restrict__ bv)
{
    __shared__ float insp[64*100];
    __shared__ float ws[8*576];
    const int tid = threadIdx.x;
    const int b  = blockIdx.x >> 4;
    const int og = (blockIdx.x & 15) * 8;

    for (int i = tid; i < 6400; i += 128) insp[i] = 0.f;
    __syncthreads();
    for (int i = tid; i < 4096; i += 128) {
        const int ic = i >> 6, pix = i & 63;
        insp[ic*100 + ((pix >> 3) + 1)*10 + (pix & 7) + 1] = g_p1[b*4096 + i];
    }
    for (int i = tid; i < 4608; i += 128) ws[i] = w[og*576 + i];
    __syncthreads();

    const int ol   = tid >> 4;
    const int o    = og + ol;
    const int quad = tid & 15;
    const int y    = quad >> 1;
    const int xh   = (quad & 1) * 4;

    float acc[4] = {0.f, 0.f, 0.f, 0.f};
    const float* wp0 = ws + ol*576;
    const float* ip0 = insp + y*10 + xh;
    for (int ic = 0; ic < 64; ic++) {
        const float* wp = wp0 + ic*9;
        const float* ip = ip0 + ic*100;
        float w0 = wp[0], w1 = wp[1], w2 = wp[2];
        float w3 = wp[3], w4 = wp[4], w5 = wp[5];
        float w6 = wp[6], w7 = wp[7], w8 = wp[8];
        float r0[6], r1[6], r2[6];
#pragma unroll
        for (int j = 0; j < 6; j++) {
            r0[j] = ip[j]; r1[j] = ip[10 + j]; r2[j] = ip[20 + j];
        }
#pragma unroll
        for (int j = 0; j < 4; j++) {
            acc[j] += w0*r0[j] + w1*r0[j+1] + w2*r0[j+2]
                    + w3*r1[j] + w4*r1[j+1] + w5*r1[j+2]
                    + w6*r2[j] + w7*r2[j+1] + w8*r2[j+2];
        }
    }
    const float inv = bg[o] * rsqrtf(bv[o] + 1e-5f);
    const float sh  = bb[o] - bm[o]*inv;
    const float bo  = bias[o];
    float* dst = g_c1 + b*8192 + o*64 + y*8 + xh;
#pragma unroll
    for (int j = 0; j < 4; j++)
        dst[j] = fmaxf((acc[j] + bo)*inv + sh, 0.f);
}

// ---------------------------------------------------------------------------
// conv2 (with fused 8x8->4x4 pool) 3x3 SAME on 4x4, 128->256, bn, relu.
// Branch-free padded 6x6 input (stride 8); thread = (o, output row), 4 px.
// ---------------------------------------------------------------------------
__global__ void __launch_bounds__(128) conv2_kernel(
    const float* __restrict__ w, const float* __restrict__ bias,
    const float* __restrict__ bg, const float* __restrict__ bb,
    const float* __restrict__ bm, const float* __restrict__ bv)
{
    __shared__ float insp[128*48];       // [ic][6 rows x 8 stride], zero-padded
    const int tid = threadIdx.x;
    const int b  = blockIdx.x >> 3;
    const int og = (blockIdx.x & 7) * 32;

    for (int i = tid; i < 6144; i += 128) insp[i] = 0.f;
    __syncthreads();
    for (int i = tid; i < 2048; i += 128) {
        const int ic = i >> 4, pix = i & 15;
        const int py = pix >> 2, px = pix & 3;
        const float* src = g_c1 + (size_t)(b*128 + ic)*64 + (py*2)*8 + px*2;
        insp[ic*48 + (py + 1)*8 + px + 1] =
            (src[0] + src[1] + src[8] + src[9]) * 0.25f;
    }
    __syncthreads();

    const int ol = tid >> 2;
    const int o  = og + ol;
    const int y  = tid & 3;

    float acc[4] = {0.f, 0.f, 0.f, 0.f};
    const float* ip0 = insp + y*8;
    const float* wpo = w + (size_t)o*128*9;
    for (int ic = 0; ic < 128; ic++) {
        const float* wp = wpo + ic*9;
        const float* ip = ip0 + ic*48;
        const float w0 = __ldg(wp),   w1 = __ldg(wp+1), w2 = __ldg(wp+2);
        const float w3 = __ldg(wp+3), w4 = __ldg(wp+4), w5 = __ldg(wp+5);
        const float w6 = __ldg(wp+6), w7 = __ldg(wp+7), w8 = __ldg(wp+8);
        float r0[6], r1[6], r2[6];
#pragma unroll
        for (int j = 0; j < 6; j++) {
            r0[j] = ip[j]; r1[j] = ip[8 + j]; r2[j] = ip[16 + j];
        }
#pragma unroll
        for (int j = 0; j < 4; j++) {
            acc[j] += w0*r0[j] + w1*r0[j+1] + w2*r0[j+2]
                    + w3*r1[j] + w4*r1[j+1] + w5*r1[j+2]
                    + w6*r2[j] + w7*r2[j+1] + w8*r2[j+2];
        }
    }
    const float inv = bg[o] * rsqrtf(bv[o] + 1e-5f);
    const float sh  = bb[o] - bm[o]*inv;
    const float bo  = bias[o];
    float* dst = g_c2 + b*4096 + o*16 + y*4;
#pragma unroll
    for (int j = 0; j < 4; j++)
        dst[j] = fmaxf((acc[j] + bo)*inv + sh, 0.f);
}

// gfeat + hierarchical heads.  block per batch.
__global__ void head_kernel(
    const float* __restrict__ w1, const float* __restrict__ b1,
    const float* __restrict__ w2, const float* __restrict__ b2,
    float* __restrict__ out)
{
    __shared__ float gfs[256];
    __shared__ float l1s[6], p1s[6], l2s[6];
    const int b = blockIdx.x, t = threadIdx.x;

    const float* p = g_c2 + b*4096 + t*16;
    float s = 0.f;
#pragma unroll
    for (int i = 0; i < 16; i++) s += p[i];
    s *= (1.f/16.f);
    gfs[t] = s;
    out[OUT_GF + b*256 + t] = s;
    __syncthreads();

    if (t < 6) {
        float a = b1[t];
        for (int c = 0; c < 256; c++) a += gfs[c] * w1[t*256 + c];
        l1s[t] = a;
        out[OUT_L1 + b*6 + t] = a;
    }
    __syncthreads();
    if (t == 0) {
        float mx = l1s[0];
#pragma unroll
        for (int i = 1; i < 6; i++) mx = fmaxf(mx, l1s[i]);
        float se = 0.f, e[6];
#pragma unroll
        for (int i = 0; i < 6; i++) { e[i] = __expf(l1s[i] - mx); se += e[i]; }
        const float rse = 1.f / se;
#pragma unroll
        for (int i = 0; i < 6; i++) {
            p1s[i] = e[i] * rse;
            out[OUT_P1 + b*6 + i] = p1s[i];
        }
    }
    __syncthreads();
    if (t < 6) {
        float a = b2[t];
        for (int c = 0; c < 256; c++) a += gfs[c] * w2[t*262 + c];
#pragma unroll
        for (int j = 0; j < 6; j++) a += p1s[j] * w2[t*262 + 256 + j];
        l2s[t] = a;
        out[OUT_L2 + b*6 + t] = a;
    }
    __syncthreads();
    if (t == 0) {
        float mx = l2s[0];
#pragma unroll
        for (int i = 1; i < 6; i++) mx = fmaxf(mx, l2s[i]);
        float se = 0.f, e[6];
#pragma unroll
        for (int i = 0; i < 6; i++) { e[i] = __expf(l2s[i] - mx); se += e[i]; }
        const float rse = 1.f / se;
#pragma unroll
        for (int i = 0; i < 6; i++) out[OUT_P2 + b*6 + i] = e[i] * rse;
    }
}

// ---------------------------------------------------------------------------
extern "C" void kernel_launch(void* const* d_in, const int* in_sizes, int n_in,
                              void* d_out, int out_size)
{
    (void)in_sizes; (void)n_in; (void)out_size;
    const float* feat = (const float*)d_in[0];
    const float* qw = (const float*)d_in[1];
    const float* qb = (const float*)d_in[2];
    const float* kw = (const float*)d_in[3];
    const float* kb = (const float*)d_in[4];
    const float* vw = (const float*)d_in[5];
    const float* vb = (const float*)d_in[6];
    const float* ow = (const float*)d_in[7];
    const float* ob = (const float*)d_in[8];
    const float* sc = (const float*)d_in[9];
    const float* c1w = (const float*)d_in[10];
    const float* c1b = (const float*)d_in[11];
    const float* bg1 = (const float*)d_in[12];
    const float* bb1 = (const float*)d_in[13];
    const float* bm1 = (const float*)d_in[14];
    const float* bv1 = (const float*)d_in[15];
    const float* c2w = (const float*)d_in[16];
    const float* c2b = (const float*)d_in[17];
    const float* bg2 = (const float*)d_in[18];
    const float* bb2 = (const float*)d_in[19];
    const float* bm2 = (const float*)d_in[20];
    const float* bv2 = (const float*)d_in[21];
    const float* w1 = (const float*)d_in[22];
    const float* b1 = (const float*)d_in[23];
    const float* w2 = (const float*)d_in[24];
    const float* b2 = (const float*)d_in[25];

    float* out = (float*)d_out;
    float* ctx = out + OUT_CTX;

    cudaFuncSetAttribute(attn_kernel,
                         cudaFuncAttributeMaxDynamicSharedMemorySize,
                         ATTN_SMEM_BYTES);

    qkv_kernel<<<256, 128>>>(feat, qw, qb, kw, kb, vw, vb);
    nop_kernel<<<1, 32>>>();
    nop_kernel<<<1, 32>>>();
    attn_kernel<<<512, 256, ATTN_SMEM_BYTES>>>(feat, ow, ob, sc, ctx);
    pool1_kernel<<<256, 256>>>(ctx);
    conv1_kernel<<<256, 128>>>(c1w, c1b, bg1, bb1, bm1, bv1);
    conv2_kernel<<<128, 128>>>(c2w, c2b, bg2, bb2, bm2, bv2);
    head_kernel<<<16, 256>>>(w1, b1, w2, b2, out);
}

// round 14
// speedup vs baseline: 1.1182x; 1.0305x over previous
#include <cuda_runtime.h>
#include <cuda_fp16.h>
#include <math.h>

#define BB 16
#define CC 64
#define HWN 4096

// output layout (floats): l1,l2,p1,p2,gfeat,context
#define OUT_L1 0
#define OUT_L2 96
#define OUT_P1 192
#define OUT_P2 288
#define OUT_GF 384
#define OUT_CTX 4480

// scratch (device globals: no allocations allowed)
__device__ unsigned g_q[BB*HWN*4];     // half2 [b][n][d/2], pre-scaled by log2e/sqrt(8)
__device__ unsigned g_k[BB*HWN*4];     // half2 [b][n][d/2]
__device__ __half   g_v[BB*CC*HWN];    // half  [b][c][n]
__device__ float g_p1[BB*CC*64];       // pooled 8x8
__device__ float g_c1[BB*128*64];      // conv1 out 8x8
__device__ float g_c2[BB*256*16];      // conv2 out 4x4

// fp16-accumulator QK mma: D (f16x2 x2) = A(16x8) * B(8x8), C = 0
__device__ __forceinline__ void mma_f16_k8_h(
    unsigned& d0, unsigned& d1,
    unsigned a0, unsigned a1, unsigned b0)
{
    asm volatile(
        "mma.sync.aligned.m16n8k8.row.col.f16.f16.f16.f16 "
        "{%0,%1}, {%2,%3}, {%4}, {%5,%5};\n"
        : "=r"(d0), "=r"(d1)
        : "r"(a0), "r"(a1), "r"(b0), "r"(0u));
}

__device__ __forceinline__ void mma_f16_k16(
    float* d,
    unsigned a0, unsigned a1, unsigned a2, unsigned a3,
    unsigned b0, unsigned b1)
{
    asm volatile(
        "mma.sync.aligned.m16n8k16.row.col.f32.f16.f16.f32 "
        "{%0,%1,%2,%3}, {%4,%5,%6,%7}, {%8,%9}, {%0,%1,%2,%3};\n"
        : "+f"(d[0]), "+f"(d[1]), "+f"(d[2]), "+f"(d[3])
        : "r"(a0), "r"(a1), "r"(a2), "r"(a3), "r"(b0), "r"(b1));
}

__device__ __forceinline__ unsigned pack2(float lo, float hi) {
    __half2 h = __floats2half2_rn(lo, hi);
    return reinterpret_cast<unsigned&>(h);
}
__device__ __forceinline__ unsigned ex2_h2(unsigned x) {
    unsigned r;
    asm("ex2.approx.f16x2 %0, %1;" : "=r"(r) : "r"(x));
    return r;
}
__device__ __forceinline__ unsigned hadd2u(unsigned a, unsigned b) {
    unsigned r;
    asm("add.f16x2 %0, %1, %2;" : "=r"(r) : "r"(a), "r"(b));
    return r;
}
__device__ __forceinline__ void ldsm_x4(
    unsigned& r0, unsigned& r1, unsigned& r2, unsigned& r3, unsigned addr)
{
    asm volatile("ldmatrix.sync.aligned.m8n8.x4.shared.b16 {%0,%1,%2,%3}, [%4];"
                 : "=r"(r0), "=r"(r1), "=r"(r2), "=r"(r3) : "r"(addr));
}
__device__ __forceinline__ unsigned su32(const void* p) {
    return (unsigned)__cvta_generic_to_shared(p);
}
#define CP_ASYNC16(dst, src) \
    asm volatile("cp.async.cg.shared.global [%0], [%1], 16;" :: "r"(dst), "l"(src))
#define CP_COMMIT() asm volatile("cp.async.commit_group;")
#define CP_WAIT0()  asm volatile("cp.async.wait_group 0;" ::: "memory")

// QK (fp16-acc) + exp for one n16 block; accumulates fp16 denominator partials.
__device__ __forceinline__ void qk_exp(
    const unsigned* kf, int kb, unsigned qa0, unsigned qa1,
    unsigned* a, unsigned& h2s0, unsigned& h2s1)
{
    unsigned p0, p1, p2, p3;
    mma_f16_k8_h(p0, p1, qa0, qa1, kf[2*kb]);
    mma_f16_k8_h(p2, p3, qa0, qa1, kf[2*kb+1]);
    a[0] = ex2_h2(p0);
    a[1] = ex2_h2(p1);
    a[2] = ex2_h2(p2);
    a[3] = ex2_h2(p3);
    h2s0 = hadd2u(h2s0, hadd2u(a[0], a[2]));
    h2s1 = hadd2u(h2s1, hadd2u(a[1], a[3]));
}

// ---------------------------------------------------------------------------
// nop spacer kernels (profiler alignment: attn at launch position 4)
// ---------------------------------------------------------------------------
__global__ void nop_kernel() {}

// ---------------------------------------------------------------------------
// QKV: fused 1x1 convs. thread = (b, 2 adjacent pixels). Outputs fp16.
// ---------------------------------------------------------------------------
__global__ void __launch_bounds__(128) qkv_kernel(
    const float* __restrict__ f,
    const float* __restrict__ qw, const float* __restrict__ qb,
    const float* __restrict__ kw, const float* __restrict__ kb,
    const float* __restrict__ vw, const float* __restrict__ vb)
{
    __shared__ float qws[512], kws[512], vws[4096];
    __shared__ float qbs[8], kbs[8], vbs[64];
    const int tid = threadIdx.x;
    for (int i = tid; i < 512; i += 128) { qws[i] = qw[i]; kws[i] = kw[i]; }
    for (int i = tid; i < 4096; i += 128) vws[i] = vw[i];
    if (tid < 8)  { qbs[tid] = qb[tid]; kbs[tid] = kb[tid]; }
    if (tid < 64) vbs[tid] = vb[tid];
    __syncthreads();

    const int gid = blockIdx.x * 128 + tid;      // 32768 pairs
    const int b = gid >> 11;
    const int n = (gid & 2047) << 1;             // even pixel

    float2 qa[8], ka[8], va[64];
#pragma unroll
    for (int i = 0; i < 8; i++) {
        qa[i] = make_float2(qbs[i], qbs[i]);
        ka[i] = make_float2(kbs[i], kbs[i]);
    }
#pragma unroll
    for (int j = 0; j < 64; j++) va[j] = make_float2(vbs[j], vbs[j]);

    const float* fp = f + (size_t)b * CC * HWN + n;
#pragma unroll 4
    for (int c = 0; c < 64; c++) {
        const float2 fv = *(const float2*)(fp + (size_t)c * HWN);
#pragma unroll
        for (int i = 0; i < 8; i++) {
            const float wq = qws[i*64 + c], wk = kws[i*64 + c];
            qa[i].x += wq * fv.x; qa[i].y += wq * fv.y;
            ka[i].x += wk * fv.x; ka[i].y += wk * fv.y;
        }
#pragma unroll
        for (int j = 0; j < 64; j++) {
            const float wv = vws[j*64 + c];
            va[j].x += wv * fv.x; va[j].y += wv * fv.y;
        }
    }
    const float ss = 0.51006975f;   // log2(e)/sqrt(8)
    uint4 u;
    u.x = pack2(qa[0].x*ss, qa[1].x*ss); u.y = pack2(qa[2].x*ss, qa[3].x*ss);
    u.z = pack2(qa[4].x*ss, qa[5].x*ss); u.w = pack2(qa[6].x*ss, qa[7].x*ss);
    ((uint4*)g_q)[b*HWN + n] = u;
    u.x = pack2(qa[0].y*ss, qa[1].y*ss); u.y = pack2(qa[2].y*ss, qa[3].y*ss);
    u.z = pack2(qa[4].y*ss, qa[5].y*ss); u.w = pack2(qa[6].y*ss, qa[7].y*ss);
    ((uint4*)g_q)[b*HWN + n + 1] = u;
    u.x = pack2(ka[0].x, ka[1].x); u.y = pack2(ka[2].x, ka[3].x);
    u.z = pack2(ka[4].x, ka[5].x); u.w = pack2(ka[6].x, ka[7].x);
    ((uint4*)g_k)[b*HWN + n] = u;
    u.x = pack2(ka[0].y, ka[1].y); u.y = pack2(ka[2].y, ka[3].y);
    u.z = pack2(ka[4].y, ka[5].y); u.w = pack2(ka[6].y, ka[7].y);
    ((uint4*)g_k)[b*HWN + n + 1] = u;
#pragma unroll
    for (int c = 0; c < 64; c++) {
        const unsigned h2 = pack2(va[c].x, va[c].y);
        *(unsigned*)(g_v + ((size_t)(b*CC + c))*HWN + n) = h2;
    }
}

// ---------------------------------------------------------------------------
// Flash-fused attention + conv_o + residual (fp16 mma, P in regs, cp.async KV).
// R14: K tile staged to smem via cp.async; K fragments via 4x ldmatrix.x4
// (replaces 16 per-tile L2 LDGs; zero register delta).
// ---------------------------------------------------------------------------
#define VROWB   272
#define VBUFB   (64*VROWB)
#define KBUF0   (2*VBUFB)               // 34816: K double buffer, 2 x 2048B
#define PS_STRIDE 132
#define OW_S    68
#define SM_OWS  8448
#define SM_DEN  (SM_OWS + 64*OW_S)
#define ATTN_SMEM_FLOATS (SM_DEN + 128)
#define ATTN_SMEM_BYTES  (ATTN_SMEM_FLOATS * 4)   // 51712 >= 34816 + 4096

__global__ void __launch_bounds__(256, 2) attn_kernel(
    const float* __restrict__ feat,
    const float* __restrict__ ow, const float* __restrict__ ob,
    const float* __restrict__ scale, float* __restrict__ ctx)
{
    extern __shared__ float sm[];
    char* smc = (char*)sm;
    float* den = sm + SM_DEN;

    const int b   = blockIdx.x >> 5;
    const int q0  = (blockIdx.x & 31) * 128;
    const int tid = threadIdx.x;
    const int w   = tid >> 5;
    const int lane = tid & 31;
    const int g   = lane >> 2;
    const int t4  = lane & 3;

    const int qrow = q0 + w*16 + g;
    const unsigned qa0 = g_q[(b*HWN + qrow)*4 + t4];
    const unsigned qa1 = g_q[(b*HWN + qrow + 8)*4 + t4];

    float o[8][4];
#pragma unroll
    for (int i = 0; i < 8; i++)
#pragma unroll
        for (int j = 0; j < 4; j++) o[i][j] = 0.f;
    float dsum0 = 0.f, dsum1 = 0.f;

    const int vc  = tid >> 2;
    const int seg = tid & 3;
    const char* gv_src = (const char*)g_v
        + 2*(((size_t)(b*CC + vc))*HWN + seg*32);
    const unsigned vdst = su32(smc) + vc*VROWB + seg*64;

    const char* gk_src = (const char*)g_k + (((size_t)b*HWN) + tid)*16;
    const unsigned kdst = su32(smc) + KBUF0 + tid*16;   // tid<128 stages K

    const int lm_m = lane >> 3, lm_r = lane & 7;
    const unsigned lm_base = su32(smc)
        + ((lm_m >> 1)*8 + lm_r)*VROWB + (lm_m & 1)*16;
    // K-fragment ldsm base: chunk c4 -> matrices 4c4..4c4+3; lane addresses
    // key = (4*c4 + lane/8)*8 + lane%8
    const unsigned klm_off = ((lane >> 3)*8 + (lane & 7))*16;

    {   // prologue: stage V+K tile 0 into buffer 0
        const char* s = gv_src;
#pragma unroll
        for (int i = 0; i < 4; i++) CP_ASYNC16(vdst + i*16, s + i*16);
        if (tid < 128) CP_ASYNC16(kdst, gk_src);
        CP_COMMIT();
    }

    for (int kt = 0; kt < 32; kt++) {
        const int k0 = kt * 128;
        CP_WAIT0();
        __syncthreads();               // V/K(kt) visible; old buffers free

        if (kt < 31) {                 // stage V+K (kt+1)
            const char* s = gv_src + 2*(size_t)(k0 + 128);
            const unsigned d = vdst + ((kt + 1) & 1) * VBUFB;
#pragma unroll
            for (int i = 0; i < 4; i++) CP_ASYNC16(d + i*16, s + i*16);
            if (tid < 128)
                CP_ASYNC16(kdst + (((kt + 1) & 1) << 11),
                           gk_src + ((size_t)(k0 + 128))*16);
            CP_COMMIT();
        }

        // K fragments from smem via ldmatrix (4 x x4 = all 16 n-blocks)
        const unsigned kbase = su32(smc) + KBUF0 + ((kt & 1) << 11) + klm_off;
        unsigned kf[16];
#pragma unroll
        for (int c4 = 0; c4 < 4; c4++)
            ldsm_x4(kf[4*c4], kf[4*c4+1], kf[4*c4+2], kf[4*c4+3],
                    kbase + c4*512);

        const unsigned bufoff = (kt & 1) * VBUFB;
        unsigned h2s0 = 0, h2s1 = 0;

        // software pipeline: exp(kb+1) overlaps PV(kb)
        unsigned acur[4], anext[4];
        qk_exp(kf, 0, qa0, qa1, acur, h2s0, h2s1);
#pragma unroll
        for (int kb = 0; kb < 8; kb++) {
            if (kb < 7) qk_exp(kf, kb + 1, qa0, qa1, anext, h2s0, h2s1);
#pragma unroll
            for (int cbp = 0; cbp < 4; cbp++) {
                unsigned v0, v1, v2, v3;
                ldsm_x4(v0, v1, v2, v3,
                        lm_base + bufoff + cbp*(16*VROWB) + kb*32);
                mma_f16_k16(o[2*cbp],     acur[0],acur[1],acur[2],acur[3], v0, v1);
                mma_f16_k16(o[2*cbp + 1], acur[0],acur[1],acur[2],acur[3], v2, v3);
            }
            if (kb < 7) {
#pragma unroll
                for (int j = 0; j < 4; j++) acur[j] = anext[j];
            }
        }

        const __half2 hh0 = *(__half2*)&h2s0;
        const __half2 hh1 = *(__half2*)&h2s1;
        const float2 f0 = __half22float2(hh0);
        const float2 f1 = __half22float2(hh1);
        dsum0 += f0.x + f0.y;
        dsum1 += f1.x + f1.y;
    }
    __syncthreads();

    dsum0 += __shfl_xor_sync(0xffffffffu, dsum0, 1);
    dsum0 += __shfl_xor_sync(0xffffffffu, dsum0, 2);
    dsum1 += __shfl_xor_sync(0xffffffffu, dsum1, 1);
    dsum1 += __shfl_xor_sync(0xffffffffu, dsum1, 2);
    if (t4 == 0) {
        den[w*16 + g]     = dsum0;
        den[w*16 + 8 + g] = dsum1;
    }

    float* attS = sm;
#pragma unroll
    for (int cb = 0; cb < 8; cb++) {
        const int cA = cb*8 + 2*t4;
        const int ql = w*16 + g;
        attS[cA*PS_STRIDE + ql]           = o[cb][0];
        attS[(cA+1)*PS_STRIDE + ql]       = o[cb][1];
        attS[cA*PS_STRIDE + ql + 8]       = o[cb][2];
        attS[(cA+1)*PS_STRIDE + ql + 8]   = o[cb][3];
    }
    float* owS = sm + SM_OWS;
#pragma unroll
    for (int i = 0; i < 16; i++) {
        const int idx = tid + i*256;
        owS[(idx & 63)*OW_S + (idx >> 6)] = ow[idx];
    }
    __syncthreads();

    const int oy = tid >> 5;
    const int qx = tid & 31;
    const float4 dv = *(const float4*)&den[qx*4];
    const float rd[4] = {1.f/dv.x, 1.f/dv.y, 1.f/dv.z, 1.f/dv.w};

    float oacc[8][4];
#pragma unroll
    for (int i = 0; i < 8; i++)
#pragma unroll
        for (int j = 0; j < 4; j++) oacc[i][j] = 0.f;

#pragma unroll 4
    for (int c = 0; c < 64; c++) {
        const float4 av = *(const float4*)&attS[c*PS_STRIDE + qx*4];
        const float4 w0 = *(const float4*)&owS[c*OW_S + oy*8];
        const float4 w1 = *(const float4*)&owS[c*OW_S + oy*8 + 4];
        const float wv[8] = {w0.x, w0.y, w0.z, w0.w, w1.x, w1.y, w1.z, w1.w};
#pragma unroll
        for (int i = 0; i < 8; i++) {
            oacc[i][0] += wv[i] * av.x;
            oacc[i][1] += wv[i] * av.y;
            oacc[i][2] += wv[i] * av.z;
            oacc[i][3] += wv[i] * av.w;
        }
    }
    const float sc = scale[0];
#pragma unroll
    for (int i = 0; i < 8; i++) {
        const int oc = oy*8 + i;
        const float obv = __ldg(&ob[oc]);
        const size_t base = ((size_t)(b*CC + oc)) * HWN + q0 + qx*4;
        const float4 f4 = *(const float4*)&feat[base];
        float4 r;
        r.x = f4.x + sc * (oacc[i][0]*rd[0] + obv);
        r.y = f4.y + sc * (oacc[i][1]*rd[1] + obv);
        r.z = f4.z + sc * (oacc[i][2]*rd[2] + obv);
        r.w = f4.w + sc * (oacc[i][3]*rd[3] + obv);
        *(float4*)&ctx[base] = r;
    }
}

// ---------------------------------------------------------------------------
// pool 64x64 -> 8x8 (one output per thread, 65536 threads)
// ---------------------------------------------------------------------------
__global__ void pool1_kernel(const float* __restrict__ ctx)
{
    const int gid = blockIdx.x * 256 + threadIdx.x;
    const int pix = gid & 63;
    const int ox = pix & 7, oy = pix >> 3;
    const int bc = gid >> 6;
    const float4* src = (const float4*)(ctx + (size_t)bc * HWN + oy*8*64 + ox*8);
    float s = 0.f;
#pragma unroll
    for (int r = 0; r < 8; r++) {
        const float4 a = src[r*16];
        const float4 c = src[r*16 + 1];
        s += (a.x + a.y + a.z + a.w) + (c.x + c.y + c.z + c.w);
    }
    g_p1[gid] = s * (1.f/64.f);
}

// ---------------------------------------------------------------------------
// conv1 3x3 SAME on 8x8, 64->128, bn, relu. padded 10x10 input.
// ---------------------------------------------------------------------------
__global__ void __launch_bounds__(128) conv1_kernel(
    const float* __restrict__ w, const float* __restrict__ bias,
    const float* __restrict__ bg, const float* __restrict__ bb,
    const float* __restrict__ bm, const float* __restrict__ bv)
{
    __shared__ float insp[64*100];
    __shared__ float ws[8*576];
    const int tid = threadIdx.x;
    const int b  = blockIdx.x >> 4;
    const int og = (blockIdx.x & 15) * 8;

    for (int i = tid; i < 6400; i += 128) insp[i] = 0.f;
    __syncthreads();
    for (int i = tid; i < 4096; i += 128) {
        const int ic = i >> 6, pix = i & 63;
        insp[ic*100 + ((pix >> 3) + 1)*10 + (pix & 7) + 1] = g_p1[b*4096 + i];
    }
    for (int i = tid; i < 4608; i += 128) ws[i] = w[og*576 + i];
    __syncthreads();

    const int ol   = tid >> 4;
    const int o    = og + ol;
    const int quad = tid & 15;
    const int y    = quad >> 1;
    const int xh   = (quad & 1) * 4;

    float acc[4] = {0.f, 0.f, 0.f, 0.f};
    const float* wp0 = ws + ol*576;
    const float* ip0 = insp + y*10 + xh;
    for (int ic = 0; ic < 64; ic++) {
        const float* wp = wp0 + ic*9;
        const float* ip = ip0 + ic*100;
        float w0 = wp[0], w1 = wp[1], w2 = wp[2];
        float w3 = wp[3], w4 = wp[4], w5 = wp[5];
        float w6 = wp[6], w7 = wp[7], w8 = wp[8];
        float r0[6], r1[6], r2[6];
#pragma unroll
        for (int j = 0; j < 6; j++) {
            r0[j] = ip[j]; r1[j] = ip[10 + j]; r2[j] = ip[20 + j];
        }
#pragma unroll
        for (int j = 0; j < 4; j++) {
            acc[j] += w0*r0[j] + w1*r0[j+1] + w2*r0[j+2]
                    + w3*r1[j] + w4*r1[j+1] + w5*r1[j+2]
                    + w6*r2[j] + w7*r2[j+1] + w8*r2[j+2];
        }
    }
    const float inv = bg[o] * rsqrtf(bv[o] + 1e-5f);
    const float sh  = bb[o] - bm[o]*inv;
    const float bo  = bias[o];
    float* dst = g_c1 + b*8192 + o*64 + y*8 + xh;
#pragma unroll
    for (int j = 0; j < 4; j++)
        dst[j] = fmaxf((acc[j] + bo)*inv + sh, 0.f);
}

// ---------------------------------------------------------------------------
// conv2 (with fused 8x8->4x4 pool) 3x3 SAME on 4x4, 128->256, bn, relu.
// ---------------------------------------------------------------------------
__global__ void __launch_bounds__(128) conv2_kernel(
    const float* __restrict__ w, const float* __restrict__ bias,
    const float* __restrict__ bg, const float* __restrict__ bb,
    const float* __restrict__ bm, const float* __restrict__ bv)
{
    __shared__ float insp[128*48];
    const int tid = threadIdx.x;
    const int b  = blockIdx.x >> 3;
    const int og = (blockIdx.x & 7) * 32;

    for (int i = tid; i < 6144; i += 128) insp[i] = 0.f;
    __syncthreads();
    for (int i = tid; i < 2048; i += 128) {
        const int ic = i >> 4, pix = i & 15;
        const int py = pix >> 2, px = pix & 3;
        const float* src = g_c1 + (size_t)(b*128 + ic)*64 + (py*2)*8 + px*2;
        insp[ic*48 + (py + 1)*8 + px + 1] =
            (src[0] + src[1] + src[8] + src[9]) * 0.25f;
    }
    __syncthreads();

    const int ol = tid >> 2;
    const int o  = og + ol;
    const int y  = tid & 3;

    float acc[4] = {0.f, 0.f, 0.f, 0.f};
    const float* ip0 = insp + y*8;
    const float* wpo = w + (size_t)o*128*9;
    for (int ic = 0; ic < 128; ic++) {
        const float* wp = wpo + ic*9;
        const float* ip = ip0 + ic*48;
        const float w0 = __ldg(wp),   w1 = __ldg(wp+1), w2 = __ldg(wp+2);
        const float w3 = __ldg(wp+3), w4 = __ldg(wp+4), w5 = __ldg(wp+5);
        const float w6 = __ldg(wp+6), w7 = __ldg(wp+7), w8 = __ldg(wp+8);
        float r0[6], r1[6], r2[6];
#pragma unroll
        for (int j = 0; j < 6; j++) {
            r0[j] = ip[j]; r1[j] = ip[8 + j]; r2[j] = ip[16 + j];
        }
#pragma unroll
        for (int j = 0; j < 4; j++) {
            acc[j] += w0*r0[j] + w1*r0[j+1] + w2*r0[j+2]
                    + w3*r1[j] + w4*r1[j+1] + w5*r1[j+2]
                    + w6*r2[j] + w7*r2[j+1] + w8*r2[j+2];
        }
    }
    const float inv = bg[o] * rsqrtf(bv[o] + 1e-5f);
    const float sh  = bb[o] - bm[o]*inv;
    const float bo  = bias[o];
    float* dst = g_c2 + b*4096 + o*16 + y*4;
#pragma unroll
    for (int j = 0; j < 4; j++)
        dst[j] = fmaxf((acc[j] + bo)*inv + sh, 0.f);
}

// gfeat + hierarchical heads.  block per batch.
__global__ void head_kernel(
    const float* __restrict__ w1, const float* __restrict__ b1,
    const float* __restrict__ w2, const float* __restrict__ b2,
    float* __restrict__ out)
{
    __shared__ float gfs[256];
    __shared__ float l1s[6], p1s[6], l2s[6];
    const int b = blockIdx.x, t = threadIdx.x;

    const float* p = g_c2 + b*4096 + t*16;
    float s = 0.f;
#pragma unroll
    for (int i = 0; i < 16; i++) s += p[i];
    s *= (1.f/16.f);
    gfs[t] = s;
    out[OUT_GF + b*256 + t] = s;
    __syncthreads();

    if (t < 6) {
        float a = b1[t];
        for (int c = 0; c < 256; c++) a += gfs[c] * w1[t*256 + c];
        l1s[t] = a;
        out[OUT_L1 + b*6 + t] = a;
    }
    __syncthreads();
    if (t == 0) {
        float mx = l1s[0];
#pragma unroll
        for (int i = 1; i < 6; i++) mx = fmaxf(mx, l1s[i]);
        float se = 0.f, e[6];
#pragma unroll
        for (int i = 0; i < 6; i++) { e[i] = __expf(l1s[i] - mx); se += e[i]; }
        const float rse = 1.f / se;
#pragma unroll
        for (int i = 0; i < 6; i++) {
            p1s[i] = e[i] * rse;
            out[OUT_P1 + b*6 + i] = p1s[i];
        }
    }
    __syncthreads();
    if (t < 6) {
        float a = b2[t];
        for (int c = 0; c < 256; c++) a += gfs[c] * w2[t*262 + c];
#pragma unroll
        for (int j = 0; j < 6; j++) a += p1s[j] * w2[t*262 + 256 + j];
        l2s[t] = a;
        out[OUT_L2 + b*6 + t] = a;
    }
    __syncthreads();
    if (t == 0) {
        float mx = l2s[0];
#pragma unroll
        for (int i = 1; i < 6; i++) mx = fmaxf(mx, l2s[i]);
        float se = 0.f, e[6];
#pragma unroll
        for (int i = 0; i < 6; i++) { e[i] = __expf(l2s[i] - mx); se += e[i]; }
        const float rse = 1.f / se;
#pragma unroll
        for (int i = 0; i < 6; i++) out[OUT_P2 + b*6 + i] = e[i] * rse;
    }
}

// ---------------------------------------------------------------------------
extern "C" void kernel_launch(void* const* d_in, const int* in_sizes, int n_in,
                              void* d_out, int out_size)
{
    (void)in_sizes; (void)n_in; (void)out_size;
    const float* feat = (const float*)d_in[0];
    const float* qw = (const float*)d_in[1];
    const float* qb = (const float*)d_in[2];
    const float* kw = (const float*)d_in[3];
    const float* kb = (const float*)d_in[4];
    const float* vw = (const float*)d_in[5];
    const float* vb = (const float*)d_in[6];
    const float* ow = (const float*)d_in[7];
    const float* ob = (const float*)d_in[8];
    const float* sc = (const float*)d_in[9];
    const float* c1w = (const float*)d_in[10];
    const float* c1b = (const float*)d_in[11];
    const float* bg1 = (const float*)d_in[12];
    const float* bb1 = (const float*)d_in[13];
    const float* bm1 = (const float*)d_in[14];
    const float* bv1 = (const float*)d_in[15];
    const float* c2w = (const float*)d_in[16];
    const float* c2b = (const float*)d_in[17];
    const float* bg2 = (const float*)d_in[18];
    const float* bb2 = (const float*)d_in[19];
    const float* bm2 = (const float*)d_in[20];
    const float* bv2 = (const float*)d_in[21];
    const float* w1 = (const float*)d_in[22];
    const float* b1 = (const float*)d_in[23];
    const float* w2 = (const float*)d_in[24];
    const float* b2 = (const float*)d_in[25];

    float* out = (float*)d_out;
    float* ctx = out + OUT_CTX;

    cudaFuncSetAttribute(attn_kernel,
                         cudaFuncAttributeMaxDynamicSharedMemorySize,
                         ATTN_SMEM_BYTES);

    qkv_kernel<<<256, 128>>>(feat, qw, qb, kw, kb, vw, vb);
    nop_kernel<<<1, 32>>>();
    nop_kernel<<<1, 32>>>();
    attn_kernel<<<512, 256, ATTN_SMEM_BYTES>>>(feat, ow, ob, sc, ctx);
    pool1_kernel<<<256, 256>>>(ctx);
    conv1_kernel<<<256, 128>>>(c1w, c1b, bg1, bb1, bm1, bv1);
    conv2_kernel<<<128, 128>>>(c2w, c2b, bg2, bb2, bm2, bv2);
    head_kernel<<<16, 256>>>(w1, b1, w2, b2, out);
}

// round 15
// speedup vs baseline: 1.1504x; 1.0288x over previous
#include <cuda_runtime.h>
#include <cuda_fp16.h>
#include <math.h>

#define BB 16
#define CC 64
#define HWN 4096

// output layout (floats): l1,l2,p1,p2,gfeat,context
#define OUT_L1 0
#define OUT_L2 96
#define OUT_P1 192
#define OUT_P2 288
#define OUT_GF 384
#define OUT_CTX 4480

// scratch (device globals: no allocations allowed)
__device__ unsigned g_q[BB*HWN*4];     // half2 [b][n][d/2], pre-scaled by log2e/sqrt(8)
__device__ unsigned g_k[BB*HWN*4];     // half2 [b][n][d/2]
__device__ __half   g_v[BB*CC*HWN];    // half  [b][c][n]
__device__ float g_p1[BB*CC*64];       // pooled 8x8
__device__ float g_c1[BB*128*64];      // conv1 out 8x8
__device__ float g_c2[BB*256*16];      // conv2 out 4x4

// fp16-accumulator QK mma: D (f16x2 x2) = A(16x8) * B(8x8), C = 0
__device__ __forceinline__ void mma_f16_k8_h(
    unsigned& d0, unsigned& d1,
    unsigned a0, unsigned a1, unsigned b0)
{
    asm volatile(
        "mma.sync.aligned.m16n8k8.row.col.f16.f16.f16.f16 "
        "{%0,%1}, {%2,%3}, {%4}, {%5,%5};\n"
        : "=r"(d0), "=r"(d1)
        : "r"(a0), "r"(a1), "r"(b0), "r"(0u));
}

// fp16-accumulator PV mma: D (f16x2 x2) += A(16x16) * B(16x8)
__device__ __forceinline__ void mma_f16_k16_h(
    unsigned& d0, unsigned& d1,
    unsigned a0, unsigned a1, unsigned a2, unsigned a3,
    unsigned b0, unsigned b1)
{
    asm volatile(
        "mma.sync.aligned.m16n8k16.row.col.f16.f16.f16.f16 "
        "{%0,%1}, {%2,%3,%4,%5}, {%6,%7}, {%0,%1};\n"
        : "+r"(d0), "+r"(d1)
        : "r"(a0), "r"(a1), "r"(a2), "r"(a3), "r"(b0), "r"(b1));
}

__device__ __forceinline__ unsigned pack2(float lo, float hi) {
    __half2 h = __floats2half2_rn(lo, hi);
    return reinterpret_cast<unsigned&>(h);
}
__device__ __forceinline__ unsigned ex2_h2(unsigned x) {
    unsigned r;
    asm("ex2.approx.f16x2 %0, %1;" : "=r"(r) : "r"(x));
    return r;
}
__device__ __forceinline__ unsigned hadd2u(unsigned a, unsigned b) {
    unsigned r;
    asm("add.f16x2 %0, %1, %2;" : "=r"(r) : "r"(a), "r"(b));
    return r;
}
__device__ __forceinline__ void ldsm_x4(
    unsigned& r0, unsigned& r1, unsigned& r2, unsigned& r3, unsigned addr)
{
    asm volatile("ldmatrix.sync.aligned.m8n8.x4.shared.b16 {%0,%1,%2,%3}, [%4];"
                 : "=r"(r0), "=r"(r1), "=r"(r2), "=r"(r3) : "r"(addr));
}
__device__ __forceinline__ unsigned su32(const void* p) {
    return (unsigned)__cvta_generic_to_shared(p);
}
#define CP_ASYNC16(dst, src) \
    asm volatile("cp.async.cg.shared.global [%0], [%1], 16;" :: "r"(dst), "l"(src))
#define CP_COMMIT() asm volatile("cp.async.commit_group;")
#define CP_WAIT0()  asm volatile("cp.async.wait_group 0;" ::: "memory")

// QK (fp16-acc) + exp for one n16 block; accumulates fp16 denominator partials.
__device__ __forceinline__ void qk_exp(
    const unsigned* kf, int kb, unsigned qa0, unsigned qa1,
    unsigned* a, unsigned& h2s0, unsigned& h2s1)
{
    unsigned p0, p1, p2, p3;
    mma_f16_k8_h(p0, p1, qa0, qa1, kf[2*kb]);
    mma_f16_k8_h(p2, p3, qa0, qa1, kf[2*kb+1]);
    a[0] = ex2_h2(p0);
    a[1] = ex2_h2(p1);
    a[2] = ex2_h2(p2);
    a[3] = ex2_h2(p3);
    h2s0 = hadd2u(h2s0, hadd2u(a[0], a[2]));
    h2s1 = hadd2u(h2s1, hadd2u(a[1], a[3]));
}

// ---------------------------------------------------------------------------
// nop spacer kernels (profiler alignment: attn at launch position 4)
// ---------------------------------------------------------------------------
__global__ void nop_kernel() {}

// ---------------------------------------------------------------------------
// QKV: fused 1x1 convs. thread = (b, 2 adjacent pixels). Outputs fp16.
// ---------------------------------------------------------------------------
__global__ void __launch_bounds__(128) qkv_kernel(
    const float* __restrict__ f,
    const float* __restrict__ qw, const float* __restrict__ qb,
    const float* __restrict__ kw, const float* __restrict__ kb,
    const float* __restrict__ vw, const float* __restrict__ vb)
{
    __shared__ float qws[512], kws[512], vws[4096];
    __shared__ float qbs[8], kbs[8], vbs[64];
    const int tid = threadIdx.x;
    for (int i = tid; i < 512; i += 128) { qws[i] = qw[i]; kws[i] = kw[i]; }
    for (int i = tid; i < 4096; i += 128) vws[i] = vw[i];
    if (tid < 8)  { qbs[tid] = qb[tid]; kbs[tid] = kb[tid]; }
    if (tid < 64) vbs[tid] = vb[tid];
    __syncthreads();

    const int gid = blockIdx.x * 128 + tid;      // 32768 pairs
    const int b = gid >> 11;
    const int n = (gid & 2047) << 1;             // even pixel

    float2 qa[8], ka[8], va[64];
#pragma unroll
    for (int i = 0; i < 8; i++) {
        qa[i] = make_float2(qbs[i], qbs[i]);
        ka[i] = make_float2(kbs[i], kbs[i]);
    }
#pragma unroll
    for (int j = 0; j < 64; j++) va[j] = make_float2(vbs[j], vbs[j]);

    const float* fp = f + (size_t)b * CC * HWN + n;
#pragma unroll 4
    for (int c = 0; c < 64; c++) {
        const float2 fv = *(const float2*)(fp + (size_t)c * HWN);
#pragma unroll
        for (int i = 0; i < 8; i++) {
            const float wq = qws[i*64 + c], wk = kws[i*64 + c];
            qa[i].x += wq * fv.x; qa[i].y += wq * fv.y;
            ka[i].x += wk * fv.x; ka[i].y += wk * fv.y;
        }
#pragma unroll
        for (int j = 0; j < 64; j++) {
            const float wv = vws[j*64 + c];
            va[j].x += wv * fv.x; va[j].y += wv * fv.y;
        }
    }
    const float ss = 0.51006975f;   // log2(e)/sqrt(8)
    uint4 u;
    u.x = pack2(qa[0].x*ss, qa[1].x*ss); u.y = pack2(qa[2].x*ss, qa[3].x*ss);
    u.z = pack2(qa[4].x*ss, qa[5].x*ss); u.w = pack2(qa[6].x*ss, qa[7].x*ss);
    ((uint4*)g_q)[b*HWN + n] = u;
    u.x = pack2(qa[0].y*ss, qa[1].y*ss); u.y = pack2(qa[2].y*ss, qa[3].y*ss);
    u.z = pack2(qa[4].y*ss, qa[5].y*ss); u.w = pack2(qa[6].y*ss, qa[7].y*ss);
    ((uint4*)g_q)[b*HWN + n + 1] = u;
    u.x = pack2(ka[0].x, ka[1].x); u.y = pack2(ka[2].x, ka[3].x);
    u.z = pack2(ka[4].x, ka[5].x); u.w = pack2(ka[6].x, ka[7].x);
    ((uint4*)g_k)[b*HWN + n] = u;
    u.x = pack2(ka[0].y, ka[1].y); u.y = pack2(ka[2].y, ka[3].y);
    u.z = pack2(ka[4].y, ka[5].y); u.w = pack2(ka[6].y, ka[7].y);
    ((uint4*)g_k)[b*HWN + n + 1] = u;
#pragma unroll
    for (int c = 0; c < 64; c++) {
        const unsigned h2 = pack2(va[c].x, va[c].y);
        *(unsigned*)(g_v + ((size_t)(b*CC + c))*HWN + n) = h2;
    }
}

// ---------------------------------------------------------------------------
// Flash-fused attention + conv_o + residual (fp16 mma, P in regs, cp.async KV).
// R15: fp16 PV accumulators (o: 32->16 regs) + per-kb hoisted V ldsm (vf[16]).
// ---------------------------------------------------------------------------
#define VROWB   272
#define VBUFB   (64*VROWB)
#define KBUF0   (2*VBUFB)               // 34816: K double buffer, 2 x 2048B
#define PS_STRIDE 132
#define OW_S    68
#define SM_OWS  8448
#define SM_DEN  (SM_OWS + 64*OW_S)
#define ATTN_SMEM_FLOATS (SM_DEN + 128)
#define ATTN_SMEM_BYTES  (ATTN_SMEM_FLOATS * 4)   // 51712 >= 34816 + 4096

__global__ void __launch_bounds__(256, 2) attn_kernel(
    const float* __restrict__ feat,
    const float* __restrict__ ow, const float* __restrict__ ob,
    const float* __restrict__ scale, float* __restrict__ ctx)
{
    extern __shared__ float sm[];
    char* smc = (char*)sm;
    float* den = sm + SM_DEN;

    const int b   = blockIdx.x >> 5;
    const int q0  = (blockIdx.x & 31) * 128;
    const int tid = threadIdx.x;
    const int w   = tid >> 5;
    const int lane = tid & 31;
    const int g   = lane >> 2;
    const int t4  = lane & 3;

    const int qrow = q0 + w*16 + g;
    const unsigned qa0 = g_q[(b*HWN + qrow)*4 + t4];
    const unsigned qa1 = g_q[(b*HWN + qrow + 8)*4 + t4];

    // PV accumulators in fp16x2: o[cb][0] = row g, o[cb][1] = row g+8
    unsigned o[8][2];
#pragma unroll
    for (int i = 0; i < 8; i++) { o[i][0] = 0u; o[i][1] = 0u; }
    float dsum0 = 0.f, dsum1 = 0.f;

    const int vc  = tid >> 2;
    const int seg = tid & 3;
    const char* gv_src = (const char*)g_v
        + 2*(((size_t)(b*CC + vc))*HWN + seg*32);
    const unsigned vdst = su32(smc) + vc*VROWB + seg*64;

    const char* gk_src = (const char*)g_k + (((size_t)b*HWN) + tid)*16;
    const unsigned kdst = su32(smc) + KBUF0 + tid*16;

    const int lm_m = lane >> 3, lm_r = lane & 7;
    const unsigned lm_base = su32(smc)
        + ((lm_m >> 1)*8 + lm_r)*VROWB + (lm_m & 1)*16;
    const unsigned klm_off = ((lane >> 3)*8 + (lane & 7))*16;

    {   // prologue: stage V+K tile 0 into buffer 0
        const char* s = gv_src;
#pragma unroll
        for (int i = 0; i < 4; i++) CP_ASYNC16(vdst + i*16, s + i*16);
        if (tid < 128) CP_ASYNC16(kdst, gk_src);
        CP_COMMIT();
    }

    for (int kt = 0; kt < 32; kt++) {
        const int k0 = kt * 128;
        CP_WAIT0();
        __syncthreads();               // V/K(kt) visible; old buffers free

        if (kt < 31) {                 // stage V+K (kt+1)
            const char* s = gv_src + 2*(size_t)(k0 + 128);
            const unsigned d = vdst + ((kt + 1) & 1) * VBUFB;
#pragma unroll
            for (int i = 0; i < 4; i++) CP_ASYNC16(d + i*16, s + i*16);
            if (tid < 128)
                CP_ASYNC16(kdst + (((kt + 1) & 1) << 11),
                           gk_src + ((size_t)(k0 + 128))*16);
            CP_COMMIT();
        }

        // K fragments from smem via ldmatrix
        const unsigned kbase = su32(smc) + KBUF0 + ((kt & 1) << 11) + klm_off;
        unsigned kf[16];
#pragma unroll
        for (int c4 = 0; c4 < 4; c4++)
            ldsm_x4(kf[4*c4], kf[4*c4+1], kf[4*c4+2], kf[4*c4+3],
                    kbase + c4*512);

        const unsigned bufoff = (kt & 1) * VBUFB;
        unsigned h2s0 = 0, h2s1 = 0;

        // software pipeline: exp(kb+1) overlaps PV(kb); V ldsm hoisted per kb
        unsigned acur[4], anext[4];
        qk_exp(kf, 0, qa0, qa1, acur, h2s0, h2s1);
#pragma unroll
        for (int kb = 0; kb < 8; kb++) {
            // hoist all 4 V ldsm of this kb (latencies overlap)
            unsigned vf[16];
#pragma unroll
            for (int cbp = 0; cbp < 4; cbp++)
                ldsm_x4(vf[4*cbp], vf[4*cbp+1], vf[4*cbp+2], vf[4*cbp+3],
                        lm_base + bufoff + cbp*(16*VROWB) + kb*32);
            if (kb < 7) qk_exp(kf, kb + 1, qa0, qa1, anext, h2s0, h2s1);
#pragma unroll
            for (int cbp = 0; cbp < 4; cbp++) {
                mma_f16_k16_h(o[2*cbp][0],   o[2*cbp][1],
                              acur[0],acur[1],acur[2],acur[3],
                              vf[4*cbp], vf[4*cbp+1]);
                mma_f16_k16_h(o[2*cbp+1][0], o[2*cbp+1][1],
                              acur[0],acur[1],acur[2],acur[3],
                              vf[4*cbp+2], vf[4*cbp+3]);
            }
            if (kb < 7) {
#pragma unroll
                for (int j = 0; j < 4; j++) acur[j] = anext[j];
            }
        }

        const __half2 hh0 = *(__half2*)&h2s0;
        const __half2 hh1 = *(__half2*)&h2s1;
        const float2 f0 = __half22float2(hh0);
        const float2 f1 = __half22float2(hh1);
        dsum0 += f0.x + f0.y;
        dsum1 += f1.x + f1.y;
    }
    __syncthreads();

    dsum0 += __shfl_xor_sync(0xffffffffu, dsum0, 1);
    dsum0 += __shfl_xor_sync(0xffffffffu, dsum0, 2);
    dsum1 += __shfl_xor_sync(0xffffffffu, dsum1, 1);
    dsum1 += __shfl_xor_sync(0xffffffffu, dsum1, 2);
    if (t4 == 0) {
        den[w*16 + g]     = dsum0;
        den[w*16 + 8 + g] = dsum1;
    }

    // numerator -> attS[c][q] (widen fp16x2 accumulators)
    float* attS = sm;
#pragma unroll
    for (int cb = 0; cb < 8; cb++) {
        const int cA = cb*8 + 2*t4;
        const int ql = w*16 + g;
        const float2 lo = __half22float2(*(__half2*)&o[cb][0]);
        const float2 hi = __half22float2(*(__half2*)&o[cb][1]);
        attS[cA*PS_STRIDE + ql]           = lo.x;
        attS[(cA+1)*PS_STRIDE + ql]       = lo.y;
        attS[cA*PS_STRIDE + ql + 8]       = hi.x;
        attS[(cA+1)*PS_STRIDE + ql + 8]   = hi.y;
    }
    float* owS = sm + SM_OWS;
#pragma unroll
    for (int i = 0; i < 16; i++) {
        const int idx = tid + i*256;
        owS[(idx & 63)*OW_S + (idx >> 6)] = ow[idx];
    }
    __syncthreads();

    const int oy = tid >> 5;
    const int qx = tid & 31;
    const float4 dv = *(const float4*)&den[qx*4];
    const float rd[4] = {1.f/dv.x, 1.f/dv.y, 1.f/dv.z, 1.f/dv.w};

    float oacc[8][4];
#pragma unroll
    for (int i = 0; i < 8; i++)
#pragma unroll
        for (int j = 0; j < 4; j++) oacc[i][j] = 0.f;

#pragma unroll 4
    for (int c = 0; c < 64; c++) {
        const float4 av = *(const float4*)&attS[c*PS_STRIDE + qx*4];
        const float4 w0 = *(const float4*)&owS[c*OW_S + oy*8];
        const float4 w1 = *(const float4*)&owS[c*OW_S + oy*8 + 4];
        const float wv[8] = {w0.x, w0.y, w0.z, w0.w, w1.x, w1.y, w1.z, w1.w};
#pragma unroll
        for (int i = 0; i < 8; i++) {
            oacc[i][0] += wv[i] * av.x;
            oacc[i][1] += wv[i] * av.y;
            oacc[i][2] += wv[i] * av.z;
            oacc[i][3] += wv[i] * av.w;
        }
    }
    const float sc = scale[0];
#pragma unroll
    for (int i = 0; i < 8; i++) {
        const int oc = oy*8 + i;
        const float obv = __ldg(&ob[oc]);
        const size_t base = ((size_t)(b*CC + oc)) * HWN + q0 + qx*4;
        const float4 f4 = *(const float4*)&feat[base];
        float4 r;
        r.x = f4.x + sc * (oacc[i][0]*rd[0] + obv);
        r.y = f4.y + sc * (oacc[i][1]*rd[1] + obv);
        r.z = f4.z + sc * (oacc[i][2]*rd[2] + obv);
        r.w = f4.w + sc * (oacc[i][3]*rd[3] + obv);
        *(float4*)&ctx[base] = r;
    }
}

// ---------------------------------------------------------------------------
// pool 64x64 -> 8x8 (one output per thread, 65536 threads)
// ---------------------------------------------------------------------------
__global__ void pool1_kernel(const float* __restrict__ ctx)
{
    const int gid = blockIdx.x * 256 + threadIdx.x;
    const int pix = gid & 63;
    const int ox = pix & 7, oy = pix >> 3;
    const int bc = gid >> 6;
    const float4* src = (const float4*)(ctx + (size_t)bc * HWN + oy*8*64 + ox*8);
    float s = 0.f;
#pragma unroll
    for (int r = 0; r < 8; r++) {
        const float4 a = src[r*16];
        const float4 c = src[r*16 + 1];
        s += (a.x + a.y + a.z + a.w) + (c.x + c.y + c.z + c.w);
    }
    g_p1[gid] = s * (1.f/64.f);
}

// ---------------------------------------------------------------------------
// conv1 3x3 SAME on 8x8, 64->128, bn, relu. padded 10x10 input.
// ---------------------------------------------------------------------------
__global__ void __launch_bounds__(128) conv1_kernel(
    const float* __restrict__ w, const float* __restrict__ bias,
    const float* __restrict__ bg, const float* __restrict__ bb,
    const float* __restrict__ bm, const float* __restrict__ bv)
{
    __shared__ float insp[64*100];
    __shared__ float ws[8*576];
    const int tid = threadIdx.x;
    const int b  = blockIdx.x >> 4;
    const int og = (blockIdx.x & 15) * 8;

    for (int i = tid; i < 6400; i += 128) insp[i] = 0.f;
    __syncthreads();
    for (int i = tid; i < 4096; i += 128) {
        const int ic = i >> 6, pix = i & 63;
        insp[ic*100 + ((pix >> 3) + 1)*10 + (pix & 7) + 1] = g_p1[b*4096 + i];
    }
    for (int i = tid; i < 4608; i += 128) ws[i] = w[og*576 + i];
    __syncthreads();

    const int ol   = tid >> 4;
    const int o    = og + ol;
    const int quad = tid & 15;
    const int y    = quad >> 1;
    const int xh   = (quad & 1) * 4;

    float acc[4] = {0.f, 0.f, 0.f, 0.f};
    const float* wp0 = ws + ol*576;
    const float* ip0 = insp + y*10 + xh;
    for (int ic = 0; ic < 64; ic++) {
        const float* wp = wp0 + ic*9;
        const float* ip = ip0 + ic*100;
        float w0 = wp[0], w1 = wp[1], w2 = wp[2];
        float w3 = wp[3], w4 = wp[4], w5 = wp[5];
        float w6 = wp[6], w7 = wp[7], w8 = wp[8];
        float r0[6], r1[6], r2[6];
#pragma unroll
        for (int j = 0; j < 6; j++) {
            r0[j] = ip[j]; r1[j] = ip[10 + j]; r2[j] = ip[20 + j];
        }
#pragma unroll
        for (int j = 0; j < 4; j++) {
            acc[j] += w0*r0[j] + w1*r0[j+1] + w2*r0[j+2]
                    + w3*r1[j] + w4*r1[j+1] + w5*r1[j+2]
                    + w6*r2[j] + w7*r2[j+1] + w8*r2[j+2];
        }
    }
    const float inv = bg[o] * rsqrtf(bv[o] + 1e-5f);
    const float sh  = bb[o] - bm[o]*inv;
    const float bo  = bias[o];
    float* dst = g_c1 + b*8192 + o*64 + y*8 + xh;
#pragma unroll
    for (int j = 0; j < 4; j++)
        dst[j] = fmaxf((acc[j] + bo)*inv + sh, 0.f);
}

// ---------------------------------------------------------------------------
// conv2 (with fused 8x8->4x4 pool) 3x3 SAME on 4x4, 128->256, bn, relu.
// ---------------------------------------------------------------------------
__global__ void __launch_bounds__(128) conv2_kernel(
    const float* __restrict__ w, const float* __restrict__ bias,
    const float* __restrict__ bg, const float* __restrict__ bb,
    const float* __restrict__ bm, const float* __restrict__ bv)
{
    __shared__ float insp[128*48];
    const int tid = threadIdx.x;
    const int b  = blockIdx.x >> 3;
    const int og = (blockIdx.x & 7) * 32;

    for (int i = tid; i < 6144; i += 128) insp[i] = 0.f;
    __syncthreads();
    for (int i = tid; i < 2048; i += 128) {
        const int ic = i >> 4, pix = i & 15;
        const int py = pix >> 2, px = pix & 3;
        const float* src = g_c1 + (size_t)(b*128 + ic)*64 + (py*2)*8 + px*2;
        insp[ic*48 + (py + 1)*8 + px + 1] =
            (src[0] + src[1] + src[8] + src[9]) * 0.25f;
    }
    __syncthreads();

    const int ol = tid >> 2;
    const int o  = og + ol;
    const int y  = tid & 3;

    float acc[4] = {0.f, 0.f, 0.f, 0.f};
    const float* ip0 = insp + y*8;
    const float* wpo = w + (size_t)o*128*9;
    for (int ic = 0; ic < 128; ic++) {
        const float* wp = wpo + ic*9;
        const float* ip = ip0 + ic*48;
        const float w0 = __ldg(wp),   w1 = __ldg(wp+1), w2 = __ldg(wp+2);
        const float w3 = __ldg(wp+3), w4 = __ldg(wp+4), w5 = __ldg(wp+5);
        const float w6 = __ldg(wp+6), w7 = __ldg(wp+7), w8 = __ldg(wp+8);
        float r0[6], r1[6], r2[6];
#pragma unroll
        for (int j = 0; j < 6; j++) {
            r0[j] = ip[j]; r1[j] = ip[8 + j]; r2[j] = ip[16 + j];
        }
#pragma unroll
        for (int j = 0; j < 4; j++) {
            acc[j] += w0*r0[j] + w1*r0[j+1] + w2*r0[j+2]
                    + w3*r1[j] + w4*r1[j+1] + w5*r1[j+2]
                    + w6*r2[j] + w7*r2[j+1] + w8*r2[j+2];
        }
    }
    const float inv = bg[o] * rsqrtf(bv[o] + 1e-5f);
    const float sh  = bb[o] - bm[o]*inv;
    const float bo  = bias[o];
    float* dst = g_c2 + b*4096 + o*16 + y*4;
#pragma unroll
    for (int j = 0; j < 4; j++)
        dst[j] = fmaxf((acc[j] + bo)*inv + sh, 0.f);
}

// gfeat + hierarchical heads.  block per batch.
__global__ void head_kernel(
    const float* __restrict__ w1, const float* __restrict__ b1,
    const float* __restrict__ w2, const float* __restrict__ b2,
    float* __restrict__ out)
{
    __shared__ float gfs[256];
    __shared__ float l1s[6], p1s[6], l2s[6];
    const int b = blockIdx.x, t = threadIdx.x;

    const float* p = g_c2 + b*4096 + t*16;
    float s = 0.f;
#pragma unroll
    for (int i = 0; i < 16; i++) s += p[i];
    s *= (1.f/16.f);
    gfs[t] = s;
    out[OUT_GF + b*256 + t] = s;
    __syncthreads();

    if (t < 6) {
        float a = b1[t];
        for (int c = 0; c < 256; c++) a += gfs[c] * w1[t*256 + c];
        l1s[t] = a;
        out[OUT_L1 + b*6 + t] = a;
    }
    __syncthreads();
    if (t == 0) {
        float mx = l1s[0];
#pragma unroll
        for (int i = 1; i < 6; i++) mx = fmaxf(mx, l1s[i]);
        float se = 0.f, e[6];
#pragma unroll
        for (int i = 0; i < 6; i++) { e[i] = __expf(l1s[i] - mx); se += e[i]; }
        const float rse = 1.f / se;
#pragma unroll
        for (int i = 0; i < 6; i++) {
            p1s[i] = e[i] * rse;
            out[OUT_P1 + b*6 + i] = p1s[i];
        }
    }
    __syncthreads();
    if (t < 6) {
        float a = b2[t];
        for (int c = 0; c < 256; c++) a += gfs[c] * w2[t*262 + c];
#pragma unroll
        for (int j = 0; j < 6; j++) a += p1s[j] * w2[t*262 + 256 + j];
        l2s[t] = a;
        out[OUT_L2 + b*6 + t] = a;
    }
    __syncthreads();
    if (t == 0) {
        float mx = l2s[0];
#pragma unroll
        for (int i = 1; i < 6; i++) mx = fmaxf(mx, l2s[i]);
        float se = 0.f, e[6];
#pragma unroll
        for (int i = 0; i < 6; i++) { e[i] = __expf(l2s[i] - mx); se += e[i]; }
        const float rse = 1.f / se;
#pragma unroll
        for (int i = 0; i < 6; i++) out[OUT_P2 + b*6 + i] = e[i] * rse;
    }
}

// ---------------------------------------------------------------------------
extern "C" void kernel_launch(void* const* d_in, const int* in_sizes, int n_in,
                              void* d_out, int out_size)
{
    (void)in_sizes; (void)n_in; (void)out_size;
    const float* feat = (const float*)d_in[0];
    const float* qw = (const float*)d_in[1];
    const float* qb = (const float*)d_in[2];
    const float* kw = (const float*)d_in[3];
    const float* kb = (const float*)d_in[4];
    const float* vw = (const float*)d_in[5];
    const float* vb = (const float*)d_in[6];
    const float* ow = (const float*)d_in[7];
    const float* ob = (const float*)d_in[8];
    const float* sc = (const float*)d_in[9];
    const float* c1w = (const float*)d_in[10];
    const float* c1b = (const float*)d_in[11];
    const float* bg1 = (const float*)d_in[12];
    const float* bb1 = (const float*)d_in[13];
    const float* bm1 = (const float*)d_in[14];
    const float* bv1 = (const float*)d_in[15];
    const float* c2w = (const float*)d_in[16];
    const float* c2b = (const float*)d_in[17];
    const float* bg2 = (const float*)d_in[18];
    const float* bb2 = (const float*)d_in[19];
    const float* bm2 = (const float*)d_in[20];
    const float* bv2 = (const float*)d_in[21];
    const float* w1 = (const float*)d_in[22];
    const float* b1 = (const float*)d_in[23];
    const float* w2 = (const float*)d_in[24];
    const float* b2 = (const float*)d_in[25];

    float* out = (float*)d_out;
    float* ctx = out + OUT_CTX;

    cudaFuncSetAttribute(attn_kernel,
                         cudaFuncAttributeMaxDynamicSharedMemorySize,
                         ATTN_SMEM_BYTES);

    qkv_kernel<<<256, 128>>>(feat, qw, qb, kw, kb, vw, vb);
    nop_kernel<<<1, 32>>>();
    nop_kernel<<<1, 32>>>();
    attn_kernel<<<512, 256, ATTN_SMEM_BYTES>>>(feat, ow, ob, sc, ctx);
    pool1_kernel<<<256, 256>>>(ctx);
    conv1_kernel<<<256, 128>>>(c1w, c1b, bg1, bb1, bm1, bv1);
    conv2_kernel<<<128, 128>>>(c2w, c2b, bg2, bb2, bm2, bv2);
    head_kernel<<<16, 256>>>(w1, b1, w2, b2, out);
}

// round 16
// speedup vs baseline: 1.1953x; 1.0391x over previous
#include <cuda_runtime.h>
#include <cuda_fp16.h>
#include <math.h>

#define BB 16
#define CC 64
#define HWN 4096

// output layout (floats): l1,l2,p1,p2,gfeat,context
#define OUT_L1 0
#define OUT_L2 96
#define OUT_P1 192
#define OUT_P2 288
#define OUT_GF 384
#define OUT_CTX 4480

// scratch (device globals: no allocations allowed)
__device__ unsigned g_q[BB*HWN*4];     // half2 [b][n][d/2], pre-scaled by log2e/sqrt(8)
__device__ unsigned g_k[BB*HWN*4];     // half2 [b][n][d/2]
__device__ __half   g_v[BB*CC*HWN];    // half  [b][c][n]
__device__ float g_p1[BB*CC*64];       // pooled 8x8
__device__ float g_c1[BB*128*64];      // conv1 out 8x8
__device__ float g_c2[BB*256*16];      // conv2 out 4x4

// fp16-accumulator QK mma: D (f16x2 x2) = A(16x8) * B(8x8), C = 0
__device__ __forceinline__ void mma_f16_k8_h(
    unsigned& d0, unsigned& d1,
    unsigned a0, unsigned a1, unsigned b0)
{
    asm volatile(
        "mma.sync.aligned.m16n8k8.row.col.f16.f16.f16.f16 "
        "{%0,%1}, {%2,%3}, {%4}, {%5,%5};\n"
        : "=r"(d0), "=r"(d1)
        : "r"(a0), "r"(a1), "r"(b0), "r"(0u));
}

// fp16-accumulator PV mma: D (f16x2 x2) += A(16x16) * B(16x8)
__device__ __forceinline__ void mma_f16_k16_h(
    unsigned& d0, unsigned& d1,
    unsigned a0, unsigned a1, unsigned a2, unsigned a3,
    unsigned b0, unsigned b1)
{
    asm volatile(
        "mma.sync.aligned.m16n8k16.row.col.f16.f16.f16.f16 "
        "{%0,%1}, {%2,%3,%4,%5}, {%6,%7}, {%0,%1};\n"
        : "+r"(d0), "+r"(d1)
        : "r"(a0), "r"(a1), "r"(a2), "r"(a3), "r"(b0), "r"(b1));
}

__device__ __forceinline__ unsigned pack2(float lo, float hi) {
    __half2 h = __floats2half2_rn(lo, hi);
    return reinterpret_cast<unsigned&>(h);
}
__device__ __forceinline__ unsigned ex2_h2(unsigned x) {
    unsigned r;
    asm("ex2.approx.f16x2 %0, %1;" : "=r"(r) : "r"(x));
    return r;
}
__device__ __forceinline__ unsigned hadd2u(unsigned a, unsigned b) {
    unsigned r;
    asm("add.f16x2 %0, %1, %2;" : "=r"(r) : "r"(a), "r"(b));
    return r;
}
__device__ __forceinline__ void ldsm_x4(
    unsigned& r0, unsigned& r1, unsigned& r2, unsigned& r3, unsigned addr)
{
    asm volatile("ldmatrix.sync.aligned.m8n8.x4.shared.b16 {%0,%1,%2,%3}, [%4];"
                 : "=r"(r0), "=r"(r1), "=r"(r2), "=r"(r3) : "r"(addr));
}
__device__ __forceinline__ unsigned su32(const void* p) {
    return (unsigned)__cvta_generic_to_shared(p);
}
#define CP_ASYNC16(dst, src) \
    asm volatile("cp.async.cg.shared.global [%0], [%1], 16;" :: "r"(dst), "l"(src))
#define CP_COMMIT() asm volatile("cp.async.commit_group;")
#define CP_WAIT0()  asm volatile("cp.async.wait_group 0;" ::: "memory")

// QK (fp16-acc) + exp for one n16 block; accumulates fp16 denominator partials.
__device__ __forceinline__ void qk_exp(
    const unsigned* kf, int kb, unsigned qa0, unsigned qa1,
    unsigned* a, unsigned& h2s0, unsigned& h2s1)
{
    unsigned p0, p1, p2, p3;
    mma_f16_k8_h(p0, p1, qa0, qa1, kf[2*kb]);
    mma_f16_k8_h(p2, p3, qa0, qa1, kf[2*kb+1]);
    a[0] = ex2_h2(p0);
    a[1] = ex2_h2(p1);
    a[2] = ex2_h2(p2);
    a[3] = ex2_h2(p3);
    h2s0 = hadd2u(h2s0, hadd2u(a[0], a[2]));
    h2s1 = hadd2u(h2s1, hadd2u(a[1], a[3]));
}

// ---------------------------------------------------------------------------
// nop spacer kernels (profiler alignment: attn at launch position 4)
// ---------------------------------------------------------------------------
__global__ void nop_kernel() {}

// ---------------------------------------------------------------------------
// QKV: fused 1x1 convs. thread = (b, 2 adjacent pixels). Outputs fp16.
// ---------------------------------------------------------------------------
__global__ void __launch_bounds__(128) qkv_kernel(
    const float* __restrict__ f,
    const float* __restrict__ qw, const float* __restrict__ qb,
    const float* __restrict__ kw, const float* __restrict__ kb,
    const float* __restrict__ vw, const float* __restrict__ vb)
{
    __shared__ float qws[512], kws[512], vws[4096];
    __shared__ float qbs[8], kbs[8], vbs[64];
    const int tid = threadIdx.x;
    for (int i = tid; i < 512; i += 128) { qws[i] = qw[i]; kws[i] = kw[i]; }
    for (int i = tid; i < 4096; i += 128) vws[i] = vw[i];
    if (tid < 8)  { qbs[tid] = qb[tid]; kbs[tid] = kb[tid]; }
    if (tid < 64) vbs[tid] = vb[tid];
    __syncthreads();

    const int gid = blockIdx.x * 128 + tid;      // 32768 pairs
    const int b = gid >> 11;
    const int n = (gid & 2047) << 1;             // even pixel

    float2 qa[8], ka[8], va[64];
#pragma unroll
    for (int i = 0; i < 8; i++) {
        qa[i] = make_float2(qbs[i], qbs[i]);
        ka[i] = make_float2(kbs[i], kbs[i]);
    }
#pragma unroll
    for (int j = 0; j < 64; j++) va[j] = make_float2(vbs[j], vbs[j]);

    const float* fp = f + (size_t)b * CC * HWN + n;
#pragma unroll 4
    for (int c = 0; c < 64; c++) {
        const float2 fv = *(const float2*)(fp + (size_t)c * HWN);
#pragma unroll
        for (int i = 0; i < 8; i++) {
            const float wq = qws[i*64 + c], wk = kws[i*64 + c];
            qa[i].x += wq * fv.x; qa[i].y += wq * fv.y;
            ka[i].x += wk * fv.x; ka[i].y += wk * fv.y;
        }
#pragma unroll
        for (int j = 0; j < 64; j++) {
            const float wv = vws[j*64 + c];
            va[j].x += wv * fv.x; va[j].y += wv * fv.y;
        }
    }
    const float ss = 0.51006975f;   // log2(e)/sqrt(8)
    uint4 u;
    u.x = pack2(qa[0].x*ss, qa[1].x*ss); u.y = pack2(qa[2].x*ss, qa[3].x*ss);
    u.z = pack2(qa[4].x*ss, qa[5].x*ss); u.w = pack2(qa[6].x*ss, qa[7].x*ss);
    ((uint4*)g_q)[b*HWN + n] = u;
    u.x = pack2(qa[0].y*ss, qa[1].y*ss); u.y = pack2(qa[2].y*ss, qa[3].y*ss);
    u.z = pack2(qa[4].y*ss, qa[5].y*ss); u.w = pack2(qa[6].y*ss, qa[7].y*ss);
    ((uint4*)g_q)[b*HWN + n + 1] = u;
    u.x = pack2(ka[0].x, ka[1].x); u.y = pack2(ka[2].x, ka[3].x);
    u.z = pack2(ka[4].x, ka[5].x); u.w = pack2(ka[6].x, ka[7].x);
    ((uint4*)g_k)[b*HWN + n] = u;
    u.x = pack2(ka[0].y, ka[1].y); u.y = pack2(ka[2].y, ka[3].y);
    u.z = pack2(ka[4].y, ka[5].y); u.w = pack2(ka[6].y, ka[7].y);
    ((uint4*)g_k)[b*HWN + n + 1] = u;
#pragma unroll
    for (int c = 0; c < 64; c++) {
        const unsigned h2 = pack2(va[c].x, va[c].y);
        *(unsigned*)(g_v + ((size_t)(b*CC + c))*HWN + n) = h2;
    }
}

// ---------------------------------------------------------------------------
// Flash-fused attention + conv_o + residual.
// R16: CTA = 256-query tile; warp owns 32 q rows (2 strips) -> V/K ldsm
// shared across strips, halving LDSM traffic per SM. grid 256.
// ---------------------------------------------------------------------------
#define VROWB   272
#define VBUFB   (64*VROWB)
#define KBUF0   (2*VBUFB)               // 34816
#define PS2     260
#define OW_S2   68
#define SM_OWS2 16640                   // floats
#define SM_DEN2 20992                   // floats
#define ATTN_SMEM_FLOATS (SM_DEN2 + 256)   // 21248
#define ATTN_SMEM_BYTES  (ATTN_SMEM_FLOATS * 4)   // 84992

__global__ void __launch_bounds__(256, 2) attn_kernel(
    const float* __restrict__ feat,
    const float* __restrict__ ow, const float* __restrict__ ob,
    const float* __restrict__ scale, float* __restrict__ ctx)
{
    extern __shared__ float sm[];
    char* smc = (char*)sm;
    float* den = sm + SM_DEN2;

    const int b   = blockIdx.x >> 4;
    const int q0  = (blockIdx.x & 15) * 256;
    const int tid = threadIdx.x;
    const int w   = tid >> 5;
    const int lane = tid & 31;
    const int g   = lane >> 2;
    const int t4  = lane & 3;

    const int qrA = q0 + w*32 + g;
    const unsigned qaA0 = g_q[(b*HWN + qrA)*4 + t4];
    const unsigned qaA1 = g_q[(b*HWN + qrA + 8)*4 + t4];
    const unsigned qaB0 = g_q[(b*HWN + qrA + 16)*4 + t4];
    const unsigned qaB1 = g_q[(b*HWN + qrA + 24)*4 + t4];

    unsigned o[16][2];
#pragma unroll
    for (int i = 0; i < 16; i++) { o[i][0] = 0u; o[i][1] = 0u; }
    float ds0 = 0.f, ds1 = 0.f, ds2 = 0.f, ds3 = 0.f;

    const int vc  = tid >> 2;
    const int seg = tid & 3;
    const char* gv_src = (const char*)g_v
        + 2*(((size_t)(b*CC + vc))*HWN + seg*32);
    const unsigned vdst = su32(smc) + vc*VROWB + seg*64;

    const char* gk_src = (const char*)g_k + (((size_t)b*HWN) + tid)*16;
    const unsigned kdst = su32(smc) + KBUF0 + tid*16;

    const int lm_m = lane >> 3, lm_r = lane & 7;
    const unsigned lm_base = su32(smc)
        + ((lm_m >> 1)*8 + lm_r)*VROWB + (lm_m & 1)*16;
    const unsigned klm_off = ((lane >> 3)*8 + (lane & 7))*16;

    {   // prologue: stage V+K tile 0
        const char* s = gv_src;
#pragma unroll
        for (int i = 0; i < 4; i++) CP_ASYNC16(vdst + i*16, s + i*16);
        if (tid < 128) CP_ASYNC16(kdst, gk_src);
        CP_COMMIT();
    }

    for (int kt = 0; kt < 32; kt++) {
        const int k0 = kt * 128;
        CP_WAIT0();
        __syncthreads();

        if (kt < 31) {
            const char* s = gv_src + 2*(size_t)(k0 + 128);
            const unsigned d = vdst + ((kt + 1) & 1) * VBUFB;
#pragma unroll
            for (int i = 0; i < 4; i++) CP_ASYNC16(d + i*16, s + i*16);
            if (tid < 128)
                CP_ASYNC16(kdst + (((kt + 1) & 1) << 11),
                           gk_src + ((size_t)(k0 + 128))*16);
            CP_COMMIT();
        }

        const unsigned kbase = su32(smc) + KBUF0 + ((kt & 1) << 11) + klm_off;
        unsigned kf[16];
#pragma unroll
        for (int c4 = 0; c4 < 4; c4++)
            ldsm_x4(kf[4*c4], kf[4*c4+1], kf[4*c4+2], kf[4*c4+3],
                    kbase + c4*512);

        const unsigned bufoff = (kt & 1) * VBUFB;
        unsigned h2s[4] = {0u, 0u, 0u, 0u};

#pragma unroll
        for (int kb = 0; kb < 8; kb++) {
            unsigned vf[16];
#pragma unroll
            for (int cbp = 0; cbp < 4; cbp++)
                ldsm_x4(vf[4*cbp], vf[4*cbp+1], vf[4*cbp+2], vf[4*cbp+3],
                        lm_base + bufoff + cbp*(16*VROWB) + kb*32);
            unsigned aA[4], aB[4];
            qk_exp(kf, kb, qaA0, qaA1, aA, h2s[0], h2s[1]);
            qk_exp(kf, kb, qaB0, qaB1, aB, h2s[2], h2s[3]);
#pragma unroll
            for (int cbp = 0; cbp < 4; cbp++) {
                mma_f16_k16_h(o[2*cbp][0],   o[2*cbp][1],
                              aA[0],aA[1],aA[2],aA[3], vf[4*cbp], vf[4*cbp+1]);
                mma_f16_k16_h(o[2*cbp+1][0], o[2*cbp+1][1],
                              aA[0],aA[1],aA[2],aA[3], vf[4*cbp+2], vf[4*cbp+3]);
            }
#pragma unroll
            for (int cbp = 0; cbp < 4; cbp++) {
                mma_f16_k16_h(o[8+2*cbp][0],   o[8+2*cbp][1],
                              aB[0],aB[1],aB[2],aB[3], vf[4*cbp], vf[4*cbp+1]);
                mma_f16_k16_h(o[8+2*cbp+1][0], o[8+2*cbp+1][1],
                              aB[0],aB[1],aB[2],aB[3], vf[4*cbp+2], vf[4*cbp+3]);
            }
        }
        {
            const float2 fA0 = __half22float2(*(__half2*)&h2s[0]);
            const float2 fA1 = __half22float2(*(__half2*)&h2s[1]);
            const float2 fB0 = __half22float2(*(__half2*)&h2s[2]);
            const float2 fB1 = __half22float2(*(__half2*)&h2s[3]);
            ds0 += fA0.x + fA0.y;
            ds1 += fA1.x + fA1.y;
            ds2 += fB0.x + fB0.y;
            ds3 += fB1.x + fB1.y;
        }
    }
    __syncthreads();

    ds0 += __shfl_xor_sync(0xffffffffu, ds0, 1);
    ds0 += __shfl_xor_sync(0xffffffffu, ds0, 2);
    ds1 += __shfl_xor_sync(0xffffffffu, ds1, 1);
    ds1 += __shfl_xor_sync(0xffffffffu, ds1, 2);
    ds2 += __shfl_xor_sync(0xffffffffu, ds2, 1);
    ds2 += __shfl_xor_sync(0xffffffffu, ds2, 2);
    ds3 += __shfl_xor_sync(0xffffffffu, ds3, 1);
    ds3 += __shfl_xor_sync(0xffffffffu, ds3, 2);
    if (t4 == 0) {
        den[w*32 + g]      = ds0;
        den[w*32 + 8 + g]  = ds1;
        den[w*32 + 16 + g] = ds2;
        den[w*32 + 24 + g] = ds3;
    }

    float* attS = sm;
#pragma unroll
    for (int cb = 0; cb < 16; cb++) {
        const int cA = (cb & 7)*8 + 2*t4;
        const int ql = w*32 + ((cb >> 3) << 4) + g;
        const float2 lo = __half22float2(*(__half2*)&o[cb][0]);
        const float2 hi = __half22float2(*(__half2*)&o[cb][1]);
        attS[cA*PS2 + ql]         = lo.x;
        attS[(cA+1)*PS2 + ql]     = lo.y;
        attS[cA*PS2 + ql + 8]     = hi.x;
        attS[(cA+1)*PS2 + ql + 8] = hi.y;
    }
    float* owS = sm + SM_OWS2;
#pragma unroll
    for (int i = 0; i < 16; i++) {
        const int idx = tid + i*256;
        owS[(idx & 63)*OW_S2 + (idx >> 6)] = ow[idx];
    }
    __syncthreads();

    const int oy = tid >> 5;
    const int qx = tid & 31;
    const float sc = scale[0];
#pragma unroll
    for (int qh = 0; qh < 2; qh++) {
        const int qoff = qh*128 + qx*4;
        const float4 dv = *(const float4*)&den[qoff];
        const float rd[4] = {1.f/dv.x, 1.f/dv.y, 1.f/dv.z, 1.f/dv.w};
        float oacc[8][4];
#pragma unroll
        for (int i = 0; i < 8; i++)
#pragma unroll
            for (int j = 0; j < 4; j++) oacc[i][j] = 0.f;
#pragma unroll 4
        for (int c = 0; c < 64; c++) {
            const float4 av = *(const float4*)&attS[c*PS2 + qoff];
            const float4 w0 = *(const float4*)&owS[c*OW_S2 + oy*8];
            const float4 w1 = *(const float4*)&owS[c*OW_S2 + oy*8 + 4];
            const float wv[8] = {w0.x, w0.y, w0.z, w0.w, w1.x, w1.y, w1.z, w1.w};
#pragma unroll
            for (int i = 0; i < 8; i++) {
                oacc[i][0] += wv[i] * av.x;
                oacc[i][1] += wv[i] * av.y;
                oacc[i][2] += wv[i] * av.z;
                oacc[i][3] += wv[i] * av.w;
            }
        }
#pragma unroll
        for (int i = 0; i < 8; i++) {
            const int oc = oy*8 + i;
            const float obv = __ldg(&ob[oc]);
            const size_t base = ((size_t)(b*CC + oc)) * HWN + q0 + qoff;
            const float4 f4 = *(const float4*)&feat[base];
            float4 r;
            r.x = f4.x + sc * (oacc[i][0]*rd[0] + obv);
            r.y = f4.y + sc * (oacc[i][1]*rd[1] + obv);
            r.z = f4.z + sc * (oacc[i][2]*rd[2] + obv);
            r.w = f4.w + sc * (oacc[i][3]*rd[3] + obv);
            *(float4*)&ctx[base] = r;
        }
    }
}

// ---------------------------------------------------------------------------
// pool 64x64 -> 8x8 (one output per thread, 65536 threads)
// ---------------------------------------------------------------------------
__global__ void pool1_kernel(const float* __restrict__ ctx)
{
    const int gid = blockIdx.x * 256 + threadIdx.x;
    const int pix = gid & 63;
    const int ox = pix & 7, oy = pix >> 3;
    const int bc = gid >> 6;
    const float4* src = (const float4*)(ctx + (size_t)bc * HWN + oy*8*64 + ox*8);
    float s = 0.f;
#pragma unroll
    for (int r = 0; r < 8; r++) {
        const float4 a = src[r*16];
        const float4 c = src[r*16 + 1];
        s += (a.x + a.y + a.z + a.w) + (c.x + c.y + c.z + c.w);
    }
    g_p1[gid] = s * (1.f/64.f);
}

// ---------------------------------------------------------------------------
// conv1 3x3 SAME on 8x8, 64->128, bn, relu. padded 10x10 input.
// ---------------------------------------------------------------------------
__global__ void __launch_bounds__(128) conv1_kernel(
    const float* __restrict__ w, const float* __restrict__ bias,
    const float* __restrict__ bg, const float* __restrict__ bb,
    const float* __restrict__ bm, const float* __restrict__ bv)
{
    __shared__ float insp[64*100];
    __shared__ float ws[8*576];
    const int tid = threadIdx.x;
    const int b  = blockIdx.x >> 4;
    const int og = (blockIdx.x & 15) * 8;

    for (int i = tid; i < 6400; i += 128) insp[i] = 0.f;
    __syncthreads();
    for (int i = tid; i < 4096; i += 128) {
        const int ic = i >> 6, pix = i & 63;
        insp[ic*100 + ((pix >> 3) + 1)*10 + (pix & 7) + 1] = g_p1[b*4096 + i];
    }
    for (int i = tid; i < 4608; i += 128) ws[i] = w[og*576 + i];
    __syncthreads();

    const int ol   = tid >> 4;
    const int o    = og + ol;
    const int quad = tid & 15;
    const int y    = quad >> 1;
    const int xh   = (quad & 1) * 4;

    float acc[4] = {0.f, 0.f, 0.f, 0.f};
    const float* wp0 = ws + ol*576;
    const float* ip0 = insp + y*10 + xh;
    for (int ic = 0; ic < 64; ic++) {
        const float* wp = wp0 + ic*9;
        const float* ip = ip0 + ic*100;
        float w0 = wp[0], w1 = wp[1], w2 = wp[2];
        float w3 = wp[3], w4 = wp[4], w5 = wp[5];
        float w6 = wp[6], w7 = wp[7], w8 = wp[8];
        float r0[6], r1[6], r2[6];
#pragma unroll
        for (int j = 0; j < 6; j++) {
            r0[j] = ip[j]; r1[j] = ip[10 + j]; r2[j] = ip[20 + j];
        }
#pragma unroll
        for (int j = 0; j < 4; j++) {
            acc[j] += w0*r0[j] + w1*r0[j+1] + w2*r0[j+2]
                    + w3*r1[j] + w4*r1[j+1] + w5*r1[j+2]
                    + w6*r2[j] + w7*r2[j+1] + w8*r2[j+2];
        }
    }
    const float inv = bg[o] * rsqrtf(bv[o] + 1e-5f);
    const float sh  = bb[o] - bm[o]*inv;
    const float bo  = bias[o];
    float* dst = g_c1 + b*8192 + o*64 + y*8 + xh;
#pragma unroll
    for (int j = 0; j < 4; j++)
        dst[j] = fmaxf((acc[j] + bo)*inv + sh, 0.f);
}

// ---------------------------------------------------------------------------
// conv2 (with fused 8x8->4x4 pool) 3x3 SAME on 4x4, 128->256, bn, relu.
// ---------------------------------------------------------------------------
__global__ void __launch_bounds__(128) conv2_kernel(
    const float* __restrict__ w, const float* __restrict__ bias,
    const float* __restrict__ bg, const float* __restrict__ bb,
    const float* __restrict__ bm, const float* __restrict__ bv)
{
    __shared__ float insp[128*48];
    const int tid = threadIdx.x;
    const int b  = blockIdx.x >> 3;
    const int og = (blockIdx.x & 7) * 32;

    for (int i = tid; i < 6144; i += 128) insp[i] = 0.f;
    __syncthreads();
    for (int i = tid; i < 2048; i += 128) {
        const int ic = i >> 4, pix = i & 15;
        const int py = pix >> 2, px = pix & 3;
        const float* src = g_c1 + (size_t)(b*128 + ic)*64 + (py*2)*8 + px*2;
        insp[ic*48 + (py + 1)*8 + px + 1] =
            (src[0] + src[1] + src[8] + src[9]) * 0.25f;
    }
    __syncthreads();

    const int ol = tid >> 2;
    const int o  = og + ol;
    const int y  = tid & 3;

    float acc[4] = {0.f, 0.f, 0.f, 0.f};
    const float* ip0 = insp + y*8;
    const float* wpo = w + (size_t)o*128*9;
    for (int ic = 0; ic < 128; ic++) {
        const float* wp = wpo + ic*9;
        const float* ip = ip0 + ic*48;
        const float w0 = __ldg(wp),   w1 = __ldg(wp+1), w2 = __ldg(wp+2);
        const float w3 = __ldg(wp+3), w4 = __ldg(wp+4), w5 = __ldg(wp+5);
        const float w6 = __ldg(wp+6), w7 = __ldg(wp+7), w8 = __ldg(wp+8);
        float r0[6], r1[6], r2[6];
#pragma unroll
        for (int j = 0; j < 6; j++) {
            r0[j] = ip[j]; r1[j] = ip[8 + j]; r2[j] = ip[16 + j];
        }
#pragma unroll
        for (int j = 0; j < 4; j++) {
            acc[j] += w0*r0[j] + w1*r0[j+1] + w2*r0[j+2]
                    + w3*r1[j] + w4*r1[j+1] + w5*r1[j+2]
                    + w6*r2[j] + w7*r2[j+1] + w8*r2[j+2];
        }
    }
    const float inv = bg[o] * rsqrtf(bv[o] + 1e-5f);
    const float sh  = bb[o] - bm[o]*inv;
    const float bo  = bias[o];
    float* dst = g_c2 + b*4096 + o*16 + y*4;
#pragma unroll
    for (int j = 0; j < 4; j++)
        dst[j] = fmaxf((acc[j] + bo)*inv + sh, 0.f);
}

// gfeat + hierarchical heads.  block per batch.
__global__ void head_kernel(
    const float* __restrict__ w1, const float* __restrict__ b1,
    const float* __restrict__ w2, const float* __restrict__ b2,
    float* __restrict__ out)
{
    __shared__ float gfs[256];
    __shared__ float l1s[6], p1s[6], l2s[6];
    const int b = blockIdx.x, t = threadIdx.x;

    const float* p = g_c2 + b*4096 + t*16;
    float s = 0.f;
#pragma unroll
    for (int i = 0; i < 16; i++) s += p[i];
    s *= (1.f/16.f);
    gfs[t] = s;
    out[OUT_GF + b*256 + t] = s;
    __syncthreads();

    if (t < 6) {
        float a = b1[t];
        for (int c = 0; c < 256; c++) a += gfs[c] * w1[t*256 + c];
        l1s[t] = a;
        out[OUT_L1 + b*6 + t] = a;
    }
    __syncthreads();
    if (t == 0) {
        float mx = l1s[0];
#pragma unroll
        for (int i = 1; i < 6; i++) mx = fmaxf(mx, l1s[i]);
        float se = 0.f, e[6];
#pragma unroll
        for (int i = 0; i < 6; i++) { e[i] = __expf(l1s[i] - mx); se += e[i]; }
        const float rse = 1.f / se;
#pragma unroll
        for (int i = 0; i < 6; i++) {
            p1s[i] = e[i] * rse;
            out[OUT_P1 + b*6 + i] = p1s[i];
        }
    }
    __syncthreads();
    if (t < 6) {
        float a = b2[t];
        for (int c = 0; c < 256; c++) a += gfs[c] * w2[t*262 + c];
#pragma unroll
        for (int j = 0; j < 6; j++) a += p1s[j] * w2[t*262 + 256 + j];
        l2s[t] = a;
        out[OUT_L2 + b*6 + t] = a;
    }
    __syncthreads();
    if (t == 0) {
        float mx = l2s[0];
#pragma unroll
        for (int i = 1; i < 6; i++) mx = fmaxf(mx, l2s[i]);
        float se = 0.f, e[6];
#pragma unroll
        for (int i = 0; i < 6; i++) { e[i] = __expf(l2s[i] - mx); se += e[i]; }
        const float rse = 1.f / se;
#pragma unroll
        for (int i = 0; i < 6; i++) out[OUT_P2 + b*6 + i] = e[i] * rse;
    }
}

// ---------------------------------------------------------------------------
extern "C" void kernel_launch(void* const* d_in, const int* in_sizes, int n_in,
                              void* d_out, int out_size)
{
    (void)in_sizes; (void)n_in; (void)out_size;
    const float* feat = (const float*)d_in[0];
    const float* qw = (const float*)d_in[1];
    const float* qb = (const float*)d_in[2];
    const float* kw = (const float*)d_in[3];
    const float* kb = (const float*)d_in[4];
    const float* vw = (const float*)d_in[5];
    const float* vb = (const float*)d_in[6];
    const float* ow = (const float*)d_in[7];
    const float* ob = (const float*)d_in[8];
    const float* sc = (const float*)d_in[9];
    const float* c1w = (const float*)d_in[10];
    const float* c1b = (const float*)d_in[11];
    const float* bg1 = (const float*)d_in[12];
    const float* bb1 = (const float*)d_in[13];
    const float* bm1 = (const float*)d_in[14];
    const float* bv1 = (const float*)d_in[15];
    const float* c2w = (const float*)d_in[16];
    const float* c2b = (const float*)d_in[17];
    const float* bg2 = (const float*)d_in[18];
    const float* bb2 = (const float*)d_in[19];
    const float* bm2 = (const float*)d_in[20];
    const float* bv2 = (const float*)d_in[21];
    const float* w1 = (const float*)d_in[22];
    const float* b1 = (const float*)d_in[23];
    const float* w2 = (const float*)d_in[24];
    const float* b2 = (const float*)d_in[25];

    float* out = (float*)d_out;
    float* ctx = out + OUT_CTX;

    cudaFuncSetAttribute(attn_kernel,
                         cudaFuncAttributeMaxDynamicSharedMemorySize,
                         ATTN_SMEM_BYTES);

    qkv_kernel<<<256, 128>>>(feat, qw, qb, kw, kb, vw, vb);
    nop_kernel<<<1, 32>>>();
    nop_kernel<<<1, 32>>>();
    attn_kernel<<<256, 256, ATTN_SMEM_BYTES>>>(feat, ow, ob, sc, ctx);
    pool1_kernel<<<256, 256>>>(ctx);
    conv1_kernel<<<256, 128>>>(c1w, c1b, bg1, bb1, bm1, bv1);
    conv2_kernel<<<128, 128>>>(c2w, c2b, bg2, bb2, bm2, bv2);
    head_kernel<<<16, 256>>>(w1, b1, w2, b2, out);
}

// round 17
// speedup vs baseline: 1.2541x; 1.0492x over previous
#include <cuda_runtime.h>
#include <cuda_fp16.h>
#include <math.h>

#define BB 16
#define CC 64
#define HWN 4096

// output layout (floats): l1,l2,p1,p2,gfeat,context
#define OUT_L1 0
#define OUT_L2 96
#define OUT_P1 192
#define OUT_P2 288
#define OUT_GF 384
#define OUT_CTX 4480

// scratch (device globals: no allocations allowed)
__device__ unsigned g_q[BB*HWN*4];     // half2 [b][n][d/2], pre-scaled by log2e/sqrt(8)
__device__ unsigned g_k[BB*HWN*4];     // half2 [b][n][d/2]
__device__ __half   g_v[BB*CC*HWN];    // half  [b][c][n]
__device__ float g_p1[BB*CC*64];       // pooled 8x8
__device__ float g_c1[BB*128*64];      // conv1 out 8x8
__device__ float g_c2[BB*256*16];      // conv2 out 4x4

// fp16-accumulator QK mma: D (f16x2 x2) = A(16x8) * B(8x8), C = 0
__device__ __forceinline__ void mma_f16_k8_h(
    unsigned& d0, unsigned& d1,
    unsigned a0, unsigned a1, unsigned b0)
{
    asm volatile(
        "mma.sync.aligned.m16n8k8.row.col.f16.f16.f16.f16 "
        "{%0,%1}, {%2,%3}, {%4}, {%5,%5};\n"
        : "=r"(d0), "=r"(d1)
        : "r"(a0), "r"(a1), "r"(b0), "r"(0u));
}

// fp16-accumulator PV mma: D (f16x2 x2) += A(16x16) * B(16x8)
__device__ __forceinline__ void mma_f16_k16_h(
    unsigned& d0, unsigned& d1,
    unsigned a0, unsigned a1, unsigned a2, unsigned a3,
    unsigned b0, unsigned b1)
{
    asm volatile(
        "mma.sync.aligned.m16n8k16.row.col.f16.f16.f16.f16 "
        "{%0,%1}, {%2,%3,%4,%5}, {%6,%7}, {%0,%1};\n"
        : "+r"(d0), "+r"(d1)
        : "r"(a0), "r"(a1), "r"(a2), "r"(a3), "r"(b0), "r"(b1));
}

__device__ __forceinline__ unsigned pack2(float lo, float hi) {
    __half2 h = __floats2half2_rn(lo, hi);
    return reinterpret_cast<unsigned&>(h);
}
__device__ __forceinline__ unsigned ex2_h2(unsigned x) {
    unsigned r;
    asm("ex2.approx.f16x2 %0, %1;" : "=r"(r) : "r"(x));
    return r;
}
__device__ __forceinline__ unsigned hadd2u(unsigned a, unsigned b) {
    unsigned r;
    asm("add.f16x2 %0, %1, %2;" : "=r"(r) : "r"(a), "r"(b));
    return r;
}
__device__ __forceinline__ void ldsm_x4(
    unsigned& r0, unsigned& r1, unsigned& r2, unsigned& r3, unsigned addr)
{
    asm volatile("ldmatrix.sync.aligned.m8n8.x4.shared.b16 {%0,%1,%2,%3}, [%4];"
                 : "=r"(r0), "=r"(r1), "=r"(r2), "=r"(r3) : "r"(addr));
}
__device__ __forceinline__ unsigned su32(const void* p) {
    return (unsigned)__cvta_generic_to_shared(p);
}
#define CP_ASYNC16(dst, src) \
    asm volatile("cp.async.cg.shared.global [%0], [%1], 16;" :: "r"(dst), "l"(src))
#define CP_COMMIT() asm volatile("cp.async.commit_group;")
#define CP_WAIT0()  asm volatile("cp.async.wait_group 0;" ::: "memory")

// QK (fp16-acc) + exp for one n16 block; accumulates fp16 denominator partials.
__device__ __forceinline__ void qk_exp(
    const unsigned* kf, int kb, unsigned qa0, unsigned qa1,
    unsigned* a, unsigned& h2s0, unsigned& h2s1)
{
    unsigned p0, p1, p2, p3;
    mma_f16_k8_h(p0, p1, qa0, qa1, kf[2*kb]);
    mma_f16_k8_h(p2, p3, qa0, qa1, kf[2*kb+1]);
    a[0] = ex2_h2(p0);
    a[1] = ex2_h2(p1);
    a[2] = ex2_h2(p2);
    a[3] = ex2_h2(p3);
    h2s0 = hadd2u(h2s0, hadd2u(a[0], a[2]));
    h2s1 = hadd2u(h2s1, hadd2u(a[1], a[3]));
}

// ---------------------------------------------------------------------------
// QKV: fused 1x1 convs. thread = (b, 2 adjacent pixels). Outputs fp16.
// ---------------------------------------------------------------------------
__global__ void __launch_bounds__(128) qkv_kernel(
    const float* __restrict__ f,
    const float* __restrict__ qw, const float* __restrict__ qb,
    const float* __restrict__ kw, const float* __restrict__ kb,
    const float* __restrict__ vw, const float* __restrict__ vb)
{
    __shared__ float qws[512], kws[512], vws[4096];
    __shared__ float qbs[8], kbs[8], vbs[64];
    const int tid = threadIdx.x;
    for (int i = tid; i < 512; i += 128) { qws[i] = qw[i]; kws[i] = kw[i]; }
    for (int i = tid; i < 4096; i += 128) vws[i] = vw[i];
    if (tid < 8)  { qbs[tid] = qb[tid]; kbs[tid] = kb[tid]; }
    if (tid < 64) vbs[tid] = vb[tid];
    __syncthreads();

    const int gid = blockIdx.x * 128 + tid;      // 32768 pairs
    const int b = gid >> 11;
    const int n = (gid & 2047) << 1;             // even pixel

    float2 qa[8], ka[8], va[64];
#pragma unroll
    for (int i = 0; i < 8; i++) {
        qa[i] = make_float2(qbs[i], qbs[i]);
        ka[i] = make_float2(kbs[i], kbs[i]);
    }
#pragma unroll
    for (int j = 0; j < 64; j++) va[j] = make_float2(vbs[j], vbs[j]);

    const float* fp = f + (size_t)b * CC * HWN + n;
#pragma unroll 4
    for (int c = 0; c < 64; c++) {
        const float2 fv = *(const float2*)(fp + (size_t)c * HWN);
#pragma unroll
        for (int i = 0; i < 8; i++) {
            const float wq = qws[i*64 + c], wk = kws[i*64 + c];
            qa[i].x += wq * fv.x; qa[i].y += wq * fv.y;
            ka[i].x += wk * fv.x; ka[i].y += wk * fv.y;
        }
#pragma unroll
        for (int j = 0; j < 64; j++) {
            const float wv = vws[j*64 + c];
            va[j].x += wv * fv.x; va[j].y += wv * fv.y;
        }
    }
    const float ss = 0.51006975f;   // log2(e)/sqrt(8)
    uint4 u;
    u.x = pack2(qa[0].x*ss, qa[1].x*ss); u.y = pack2(qa[2].x*ss, qa[3].x*ss);
    u.z = pack2(qa[4].x*ss, qa[5].x*ss); u.w = pack2(qa[6].x*ss, qa[7].x*ss);
    ((uint4*)g_q)[b*HWN + n] = u;
    u.x = pack2(qa[0].y*ss, qa[1].y*ss); u.y = pack2(qa[2].y*ss, qa[3].y*ss);
    u.z = pack2(qa[4].y*ss, qa[5].y*ss); u.w = pack2(qa[6].y*ss, qa[7].y*ss);
    ((uint4*)g_q)[b*HWN + n + 1] = u;
    u.x = pack2(ka[0].x, ka[1].x); u.y = pack2(ka[2].x, ka[3].x);
    u.z = pack2(ka[4].x, ka[5].x); u.w = pack2(ka[6].x, ka[7].x);
    ((uint4*)g_k)[b*HWN + n] = u;
    u.x = pack2(ka[0].y, ka[1].y); u.y = pack2(ka[2].y, ka[3].y);
    u.z = pack2(ka[4].y, ka[5].y); u.w = pack2(ka[6].y, ka[7].y);
    ((uint4*)g_k)[b*HWN + n + 1] = u;
#pragma unroll
    for (int c = 0; c < 64; c++) {
        const unsigned h2 = pack2(va[c].x, va[c].y);
        *(unsigned*)(g_v + ((size_t)(b*CC + c))*HWN + n) = h2;
    }
}

// ---------------------------------------------------------------------------
// Flash-fused attention + conv_o + residual.
// CTA = 256-query tile; warp owns 32 q rows (2 strips); V/K ldsm shared.
// (byte-identical mainloop to the validated 167.7us R16 kernel)
// ---------------------------------------------------------------------------
#define VROWB   272
#define VBUFB   (64*VROWB)
#define KBUF0   (2*VBUFB)               // 34816
#define PS2     260
#define OW_S2   68
#define SM_OWS2 16640                   // floats
#define SM_DEN2 20992                   // floats
#define ATTN_SMEM_FLOATS (SM_DEN2 + 256)   // 21248
#define ATTN_SMEM_BYTES  (ATTN_SMEM_FLOATS * 4)   // 84992

__global__ void __launch_bounds__(256, 2) attn_kernel(
    const float* __restrict__ feat,
    const float* __restrict__ ow, const float* __restrict__ ob,
    const float* __restrict__ scale, float* __restrict__ ctx)
{
    extern __shared__ float sm[];
    char* smc = (char*)sm;
    float* den = sm + SM_DEN2;

    const int b   = blockIdx.x >> 4;
    const int q0  = (blockIdx.x & 15) * 256;
    const int tid = threadIdx.x;
    const int w   = tid >> 5;
    const int lane = tid & 31;
    const int g   = lane >> 2;
    const int t4  = lane & 3;

    const int qrA = q0 + w*32 + g;
    const unsigned qaA0 = g_q[(b*HWN + qrA)*4 + t4];
    const unsigned qaA1 = g_q[(b*HWN + qrA + 8)*4 + t4];
    const unsigned qaB0 = g_q[(b*HWN + qrA + 16)*4 + t4];
    const unsigned qaB1 = g_q[(b*HWN + qrA + 24)*4 + t4];

    unsigned o[16][2];
#pragma unroll
    for (int i = 0; i < 16; i++) { o[i][0] = 0u; o[i][1] = 0u; }
    float ds0 = 0.f, ds1 = 0.f, ds2 = 0.f, ds3 = 0.f;

    const int vc  = tid >> 2;
    const int seg = tid & 3;
    const char* gv_src = (const char*)g_v
        + 2*(((size_t)(b*CC + vc))*HWN + seg*32);
    const unsigned vdst = su32(smc) + vc*VROWB + seg*64;

    const char* gk_src = (const char*)g_k + (((size_t)b*HWN) + tid)*16;
    const unsigned kdst = su32(smc) + KBUF0 + tid*16;

    const int lm_m = lane >> 3, lm_r = lane & 7;
    const unsigned lm_base = su32(smc)
        + ((lm_m >> 1)*8 + lm_r)*VROWB + (lm_m & 1)*16;
    const unsigned klm_off = ((lane >> 3)*8 + (lane & 7))*16;

    {   // prologue: stage V+K tile 0
        const char* s = gv_src;
#pragma unroll
        for (int i = 0; i < 4; i++) CP_ASYNC16(vdst + i*16, s + i*16);
        if (tid < 128) CP_ASYNC16(kdst, gk_src);
        CP_COMMIT();
    }

    for (int kt = 0; kt < 32; kt++) {
        const int k0 = kt * 128;
        CP_WAIT0();
        __syncthreads();

        if (kt < 31) {
            const char* s = gv_src + 2*(size_t)(k0 + 128);
            const unsigned d = vdst + ((kt + 1) & 1) * VBUFB;
#pragma unroll
            for (int i = 0; i < 4; i++) CP_ASYNC16(d + i*16, s + i*16);
            if (tid < 128)
                CP_ASYNC16(kdst + (((kt + 1) & 1) << 11),
                           gk_src + ((size_t)(k0 + 128))*16);
            CP_COMMIT();
        }

        const unsigned kbase = su32(smc) + KBUF0 + ((kt & 1) << 11) + klm_off;
        unsigned kf[16];
#pragma unroll
        for (int c4 = 0; c4 < 4; c4++)
            ldsm_x4(kf[4*c4], kf[4*c4+1], kf[4*c4+2], kf[4*c4+3],
                    kbase + c4*512);

        const unsigned bufoff = (kt & 1) * VBUFB;
        unsigned h2s[4] = {0u, 0u, 0u, 0u};

#pragma unroll
        for (int kb = 0; kb < 8; kb++) {
            unsigned vf[16];
#pragma unroll
            for (int cbp = 0; cbp < 4; cbp++)
                ldsm_x4(vf[4*cbp], vf[4*cbp+1], vf[4*cbp+2], vf[4*cbp+3],
                        lm_base + bufoff + cbp*(16*VROWB) + kb*32);
            unsigned aA[4], aB[4];
            qk_exp(kf, kb, qaA0, qaA1, aA, h2s[0], h2s[1]);
            qk_exp(kf, kb, qaB0, qaB1, aB, h2s[2], h2s[3]);
#pragma unroll
            for (int cbp = 0; cbp < 4; cbp++) {
                mma_f16_k16_h(o[2*cbp][0],   o[2*cbp][1],
                              aA[0],aA[1],aA[2],aA[3], vf[4*cbp], vf[4*cbp+1]);
                mma_f16_k16_h(o[2*cbp+1][0], o[2*cbp+1][1],
                              aA[0],aA[1],aA[2],aA[3], vf[4*cbp+2], vf[4*cbp+3]);
            }
#pragma unroll
            for (int cbp = 0; cbp < 4; cbp++) {
                mma_f16_k16_h(o[8+2*cbp][0],   o[8+2*cbp][1],
                              aB[0],aB[1],aB[2],aB[3], vf[4*cbp], vf[4*cbp+1]);
                mma_f16_k16_h(o[8+2*cbp+1][0], o[8+2*cbp+1][1],
                              aB[0],aB[1],aB[2],aB[3], vf[4*cbp+2], vf[4*cbp+3]);
            }
        }
        {
            const float2 fA0 = __half22float2(*(__half2*)&h2s[0]);
            const float2 fA1 = __half22float2(*(__half2*)&h2s[1]);
            const float2 fB0 = __half22float2(*(__half2*)&h2s[2]);
            const float2 fB1 = __half22float2(*(__half2*)&h2s[3]);
            ds0 += fA0.x + fA0.y;
            ds1 += fA1.x + fA1.y;
            ds2 += fB0.x + fB0.y;
            ds3 += fB1.x + fB1.y;
        }
    }
    __syncthreads();

    ds0 += __shfl_xor_sync(0xffffffffu, ds0, 1);
    ds0 += __shfl_xor_sync(0xffffffffu, ds0, 2);
    ds1 += __shfl_xor_sync(0xffffffffu, ds1, 1);
    ds1 += __shfl_xor_sync(0xffffffffu, ds1, 2);
    ds2 += __shfl_xor_sync(0xffffffffu, ds2, 1);
    ds2 += __shfl_xor_sync(0xffffffffu, ds2, 2);
    ds3 += __shfl_xor_sync(0xffffffffu, ds3, 1);
    ds3 += __shfl_xor_sync(0xffffffffu, ds3, 2);
    if (t4 == 0) {
        den[w*32 + g]      = ds0;
        den[w*32 + 8 + g]  = ds1;
        den[w*32 + 16 + g] = ds2;
        den[w*32 + 24 + g] = ds3;
    }

    float* attS = sm;
#pragma unroll
    for (int cb = 0; cb < 16; cb++) {
        const int cA = (cb & 7)*8 + 2*t4;
        const int ql = w*32 + ((cb >> 3) << 4) + g;
        const float2 lo = __half22float2(*(__half2*)&o[cb][0]);
        const float2 hi = __half22float2(*(__half2*)&o[cb][1]);
        attS[cA*PS2 + ql]         = lo.x;
        attS[(cA+1)*PS2 + ql]     = lo.y;
        attS[cA*PS2 + ql + 8]     = hi.x;
        attS[(cA+1)*PS2 + ql + 8] = hi.y;
    }
    float* owS = sm + SM_OWS2;
#pragma unroll
    for (int i = 0; i < 16; i++) {
        const int idx = tid + i*256;
        owS[(idx & 63)*OW_S2 + (idx >> 6)] = ow[idx];
    }
    __syncthreads();

    const int oy = tid >> 5;
    const int qx = tid & 31;
    const float sc = scale[0];
#pragma unroll
    for (int qh = 0; qh < 2; qh++) {
        const int qoff = qh*128 + qx*4;
        const float4 dv = *(const float4*)&den[qoff];
        const float rd[4] = {1.f/dv.x, 1.f/dv.y, 1.f/dv.z, 1.f/dv.w};
        float oacc[8][4];
#pragma unroll
        for (int i = 0; i < 8; i++)
#pragma unroll
            for (int j = 0; j < 4; j++) oacc[i][j] = 0.f;
#pragma unroll 4
        for (int c = 0; c < 64; c++) {
            const float4 av = *(const float4*)&attS[c*PS2 + qoff];
            const float4 w0 = *(const float4*)&owS[c*OW_S2 + oy*8];
            const float4 w1 = *(const float4*)&owS[c*OW_S2 + oy*8 + 4];
            const float wv[8] = {w0.x, w0.y, w0.z, w0.w, w1.x, w1.y, w1.z, w1.w};
#pragma unroll
            for (int i = 0; i < 8; i++) {
                oacc[i][0] += wv[i] * av.x;
                oacc[i][1] += wv[i] * av.y;
                oacc[i][2] += wv[i] * av.z;
                oacc[i][3] += wv[i] * av.w;
            }
        }
#pragma unroll
        for (int i = 0; i < 8; i++) {
            const int oc = oy*8 + i;
            const float obv = __ldg(&ob[oc]);
            const size_t base = ((size_t)(b*CC + oc)) * HWN + q0 + qoff;
            const float4 f4 = *(const float4*)&feat[base];
            float4 r;
            r.x = f4.x + sc * (oacc[i][0]*rd[0] + obv);
            r.y = f4.y + sc * (oacc[i][1]*rd[1] + obv);
            r.z = f4.z + sc * (oacc[i][2]*rd[2] + obv);
            r.w = f4.w + sc * (oacc[i][3]*rd[3] + obv);
            *(float4*)&ctx[base] = r;
        }
    }
}

// ---------------------------------------------------------------------------
// pool 64x64 -> 8x8 (one output per thread, 65536 threads)
// ---------------------------------------------------------------------------
__global__ void pool1_kernel(const float* __restrict__ ctx)
{
    const int gid = blockIdx.x * 256 + threadIdx.x;
    const int pix = gid & 63;
    const int ox = pix & 7, oy = pix >> 3;
    const int bc = gid >> 6;
    const float4* src = (const float4*)(ctx + (size_t)bc * HWN + oy*8*64 + ox*8);
    float s = 0.f;
#pragma unroll
    for (int r = 0; r < 8; r++) {
        const float4 a = src[r*16];
        const float4 c = src[r*16 + 1];
        s += (a.x + a.y + a.z + a.w) + (c.x + c.y + c.z + c.w);
    }
    g_p1[gid] = s * (1.f/64.f);
}

// ---------------------------------------------------------------------------
// conv1 3x3 SAME on 8x8, 64->128, bn, relu. padded 10x10 input.
// ---------------------------------------------------------------------------
__global__ void __launch_bounds__(128) conv1_kernel(
    const float* __restrict__ w, const float* __restrict__ bias,
    const float* __restrict__ bg, const float* __restrict__ bb,
    const float* __restrict__ bm, const float* __restrict__ bv)
{
    __shared__ float insp[64*100];
    __shared__ float ws[8*576];
    const int tid = threadIdx.x;
    const int b  = blockIdx.x >> 4;
    const int og = (blockIdx.x & 15) * 8;

    for (int i = tid; i < 6400; i += 128) insp[i] = 0.f;
    __syncthreads();
    for (int i = tid; i < 4096; i += 128) {
        const int ic = i >> 6, pix = i & 63;
        insp[ic*100 + ((pix >> 3) + 1)*10 + (pix & 7) + 1] = g_p1[b*4096 + i];
    }
    for (int i = tid; i < 4608; i += 128) ws[i] = w[og*576 + i];
    __syncthreads();

    const int ol   = tid >> 4;
    const int o    = og + ol;
    const int quad = tid & 15;
    const int y    = quad >> 1;
    const int xh   = (quad & 1) * 4;

    float acc[4] = {0.f, 0.f, 0.f, 0.f};
    const float* wp0 = ws + ol*576;
    const float* ip0 = insp + y*10 + xh;
    for (int ic = 0; ic < 64; ic++) {
        const float* wp = wp0 + ic*9;
        const float* ip = ip0 + ic*100;
        float w0 = wp[0], w1 = wp[1], w2 = wp[2];
        float w3 = wp[3], w4 = wp[4], w5 = wp[5];
        float w6 = wp[6], w7 = wp[7], w8 = wp[8];
        float r0[6], r1[6], r2[6];
#pragma unroll
        for (int j = 0; j < 6; j++) {
            r0[j] = ip[j]; r1[j] = ip[10 + j]; r2[j] = ip[20 + j];
        }
#pragma unroll
        for (int j = 0; j < 4; j++) {
            acc[j] += w0*r0[j] + w1*r0[j+1] + w2*r0[j+2]
                    + w3*r1[j] + w4*r1[j+1] + w5*r1[j+2]
                    + w6*r2[j] + w7*r2[j+1] + w8*r2[j+2];
        }
    }
    const float inv = bg[o] * rsqrtf(bv[o] + 1e-5f);
    const float sh  = bb[o] - bm[o]*inv;
    const float bo  = bias[o];
    float* dst = g_c1 + b*8192 + o*64 + y*8 + xh;
#pragma unroll
    for (int j = 0; j < 4; j++)
        dst[j] = fmaxf((acc[j] + bo)*inv + sh, 0.f);
}

// ---------------------------------------------------------------------------
// conv2 (with fused 8x8->4x4 pool) 3x3 SAME on 4x4, 128->256, bn, relu.
// ---------------------------------------------------------------------------
__global__ void __launch_bounds__(128) conv2_kernel(
    const float* __restrict__ w, const float* __restrict__ bias,
    const float* __restrict__ bg, const float* __restrict__ bb,
    const float* __restrict__ bm, const float* __restrict__ bv)
{
    __shared__ float insp[128*48];
    const int tid = threadIdx.x;
    const int b  = blockIdx.x >> 3;
    const int og = (blockIdx.x & 7) * 32;

    for (int i = tid; i < 6144; i += 128) insp[i] = 0.f;
    __syncthreads();
    for (int i = tid; i < 2048; i += 128) {
        const int ic = i >> 4, pix = i & 15;
        const int py = pix >> 2, px = pix & 3;
        const float* src = g_c1 + (size_t)(b*128 + ic)*64 + (py*2)*8 + px*2;
        insp[ic*48 + (py + 1)*8 + px + 1] =
            (src[0] + src[1] + src[8] + src[9]) * 0.25f;
    }
    __syncthreads();

    const int ol = tid >> 2;
    const int o  = og + ol;
    const int y  = tid & 3;

    float acc[4] = {0.f, 0.f, 0.f, 0.f};
    const float* ip0 = insp + y*8;
    const float* wpo = w + (size_t)o*128*9;
    for (int ic = 0; ic < 128; ic++) {
        const float* wp = wpo + ic*9;
        const float* ip = ip0 + ic*48;
        const float w0 = __ldg(wp),   w1 = __ldg(wp+1), w2 = __ldg(wp+2);
        const float w3 = __ldg(wp+3), w4 = __ldg(wp+4), w5 = __ldg(wp+5);
        const float w6 = __ldg(wp+6), w7 = __ldg(wp+7), w8 = __ldg(wp+8);
        float r0[6], r1[6], r2[6];
#pragma unroll
        for (int j = 0; j < 6; j++) {
            r0[j] = ip[j]; r1[j] = ip[8 + j]; r2[j] = ip[16 + j];
        }
#pragma unroll
        for (int j = 0; j < 4; j++) {
            acc[j] += w0*r0[j] + w1*r0[j+1] + w2*r0[j+2]
                    + w3*r1[j] + w4*r1[j+1] + w5*r1[j+2]
                    + w6*r2[j] + w7*r2[j+1] + w8*r2[j+2];
        }
    }
    const float inv = bg[o] * rsqrtf(bv[o] + 1e-5f);
    const float sh  = bb[o] - bm[o]*inv;
    const float bo  = bias[o];
    float* dst = g_c2 + b*4096 + o*16 + y*4;
#pragma unroll
    for (int j = 0; j < 4; j++)
        dst[j] = fmaxf((acc[j] + bo)*inv + sh, 0.f);
}

// ---------------------------------------------------------------------------
// gfeat + hierarchical heads. block per batch; warp-parallel dot products.
// ---------------------------------------------------------------------------
__global__ void head_kernel(
    const float* __restrict__ w1, const float* __restrict__ b1,
    const float* __restrict__ w2, const float* __restrict__ b2,
    float* __restrict__ out)
{
    __shared__ float gfs[256];
    __shared__ float l1s[6], p1s[6], l2s[6];
    const int b = blockIdx.x, t = threadIdx.x;
    const int wid = t >> 5, lane = t & 31;

    const float* p = g_c2 + b*4096 + t*16;
    float s = 0.f;
#pragma unroll
    for (int i = 0; i < 16; i++) s += p[i];
    s *= (1.f/16.f);
    gfs[t] = s;
    out[OUT_GF + b*256 + t] = s;
    __syncthreads();

    // l1: warp wid<6 computes class wid
    if (wid < 6) {
        float a = 0.f;
#pragma unroll
        for (int c = lane; c < 256; c += 32) a += gfs[c] * w1[wid*256 + c];
        a += __shfl_xor_sync(0xffffffffu, a, 16);
        a += __shfl_xor_sync(0xffffffffu, a, 8);
        a += __shfl_xor_sync(0xffffffffu, a, 4);
        a += __shfl_xor_sync(0xffffffffu, a, 2);
        a += __shfl_xor_sync(0xffffffffu, a, 1);
        if (lane == 0) {
            const float l = a + b1[wid];
            l1s[wid] = l;
            out[OUT_L1 + b*6 + wid] = l;
        }
    }
    __syncthreads();
    if (t == 0) {
        float mx = l1s[0];
#pragma unroll
        for (int i = 1; i < 6; i++) mx = fmaxf(mx, l1s[i]);
        float se = 0.f, e[6];
#pragma unroll
        for (int i = 0; i < 6; i++) { e[i] = __expf(l1s[i] - mx); se += e[i]; }
        const float rse = 1.f / se;
#pragma unroll
        for (int i = 0; i < 6; i++) {
            p1s[i] = e[i] * rse;
            out[OUT_P1 + b*6 + i] = p1s[i];
        }
    }
    __syncthreads();
    // l2: warp wid<6 computes class wid (gfeat part), lane0 adds p1 terms
    if (wid < 6) {
        float a = 0.f;
#pragma unroll
        for (int c = lane; c < 256; c += 32) a += gfs[c] * w2[wid*262 + c];
        a += __shfl_xor_sync(0xffffffffu, a, 16);
        a += __shfl_xor_sync(0xffffffffu, a, 8);
        a += __shfl_xor_sync(0xffffffffu, a, 4);
        a += __shfl_xor_sync(0xffffffffu, a, 2);
        a += __shfl_xor_sync(0xffffffffu, a, 1);
        if (lane == 0) {
            float l = a + b2[wid];
#pragma unroll
            for (int j = 0; j < 6; j++) l += p1s[j] * w2[wid*262 + 256 + j];
            l2s[wid] = l;
            out[OUT_L2 + b*6 + wid] = l;
        }
    }
    __syncthreads();
    if (t == 0) {
        float mx = l2s[0];
#pragma unroll
        for (int i = 1; i < 6; i++) mx = fmaxf(mx, l2s[i]);
        float se = 0.f, e[6];
#pragma unroll
        for (int i = 0; i < 6; i++) { e[i] = __expf(l2s[i] - mx); se += e[i]; }
        const float rse = 1.f / se;
#pragma unroll
        for (int i = 0; i < 6; i++) out[OUT_P2 + b*6 + i] = e[i] * rse;
    }
}

// ---------------------------------------------------------------------------
extern "C" void kernel_launch(void* const* d_in, const int* in_sizes, int n_in,
                              void* d_out, int out_size)
{
    (void)in_sizes; (void)n_in; (void)out_size;
    const float* feat = (const float*)d_in[0];
    const float* qw = (const float*)d_in[1];
    const float* qb = (const float*)d_in[2];
    const float* kw = (const float*)d_in[3];
    const float* kb = (const float*)d_in[4];
    const float* vw = (const float*)d_in[5];
    const float* vb = (const float*)d_in[6];
    const float* ow = (const float*)d_in[7];
    const float* ob = (const float*)d_in[8];
    const float* sc = (const float*)d_in[9];
    const float* c1w = (const float*)d_in[10];
    const float* c1b = (const float*)d_in[11];
    const float* bg1 = (const float*)d_in[12];
    const float* bb1 = (const float*)d_in[13];
    const float* bm1 = (const float*)d_in[14];
    const float* bv1 = (const float*)d_in[15];
    const float* c2w = (const float*)d_in[16];
    const float* c2b = (const float*)d_in[17];
    const float* bg2 = (const float*)d_in[18];
    const float* bb2 = (const float*)d_in[19];
    const float* bm2 = (const float*)d_in[20];
    const float* bv2 = (const float*)d_in[21];
    const float* w1 = (const float*)d_in[22];
    const float* b1 = (const float*)d_in[23];
    const float* w2 = (const float*)d_in[24];
    const float* b2 = (const float*)d_in[25];

    float* out = (float*)d_out;
    float* ctx = out + OUT_CTX;

    cudaFuncSetAttribute(attn_kernel,
                         cudaFuncAttributeMaxDynamicSharedMemorySize,
                         ATTN_SMEM_BYTES);

    qkv_kernel<<<256, 128>>>(feat, qw, qb, kw, kb, vw, vb);
    attn_kernel<<<256, 256, ATTN_SMEM_BYTES>>>(feat, ow, ob, sc, ctx);
    pool1_kernel<<<256, 256>>>(ctx);
    conv1_kernel<<<256, 128>>>(c1w, c1b, bg1, bb1, bm1, bv1);
    conv2_kernel<<<128, 128>>>(c2w, c2b, bg2, bb2, bm2, bv2);
    head_kernel<<<16, 256>>>(w1, b1, w2, b2, out);
}